// round 11
// baseline (speedup 1.0000x reference)
#include <cuda_runtime.h>
#include <cuda_bf16.h>
#include <stdint.h>
#include <math.h>

typedef unsigned int u32;

// ---------------- problem constants ----------------
#define Nn      16384
#define Ee      131072
#define ETOT    (Ee + Nn)
#define Bsz     256
#define Lseq    64
#define Hd      256
#define NHEADS  8
#define F1      2048
#define G4      1024
#define NNODE_  37000

#define LSTM_BLOCKS 128

// ---------------- device scratch ----------------
__device__ float g_h1  [(size_t)Nn * F1];
__device__ float g_h2  [(size_t)Nn * Hd];
__device__ float g_xg  [(size_t)Nn * G4];
__device__ float g_as1 [Nn * NHEADS];
__device__ float g_ad1 [Nn * NHEADS];
__device__ float g_as2 [Nn];
__device__ float g_ad2 [Nn];
__device__ int   g_counts[Nn];
__device__ int   g_rowptr[Nn + 1];
__device__ int   g_cursor[Nn];
__device__ int   g_colsrc[ETOT];
__device__ int   g_len   [Bsz];
__device__ int   g_starts[Bsz];
__device__ int   g_nodeidx[Bsz * Lseq];
__device__ float g_hbuf1[Bsz * Hd];
__device__ float g_h    [Bsz * Hd];
__device__ float g_bsum [G4];
__device__ unsigned g_bar_arrive = 0;
__device__ unsigned g_bar_gen    = 0;

// bf16 hi/lo split operands for tensor-core GEMMs
__device__ __nv_bfloat16 g_x0h[(size_t)Nn * Hd],  g_x0l[(size_t)Nn * Hd];
__device__ __nv_bfloat16 g_x1h[(size_t)Nn * F1],  g_x1l[(size_t)Nn * F1];
__device__ __nv_bfloat16 g_o2h[(size_t)Nn * Hd],  g_o2l[(size_t)Nn * Hd];
__device__ __nv_bfloat16 g_W1Th[(size_t)F1 * Hd], g_W1Tl[(size_t)F1 * Hd];
__device__ __nv_bfloat16 g_W2Th[(size_t)Hd * F1], g_W2Tl[(size_t)Hd * F1];
__device__ __nv_bfloat16 g_Wihh[(size_t)G4 * Hd], g_Wihl[(size_t)G4 * Hd];
__device__ __nv_bfloat16 g_hTh[Bsz * Hd],         g_hTl[Bsz * Hd];
__device__ __nv_bfloat16 g_Wph[(size_t)NNODE_ * Hd], g_Wpl[(size_t)NNODE_ * Hd];

// ---------------- small helpers ----------------
__device__ __forceinline__ void split_bf16(float v, __nv_bfloat16& h, __nv_bfloat16& l)
{
    h = __float2bfloat16(v);
    l = __float2bfloat16(v - __bfloat162float(h));
}
__device__ __forceinline__ u32 smem_u32(const void* p)
{
    return (u32)__cvta_generic_to_shared(p);
}
__device__ __forceinline__ void cp16(u32 dst, const void* src, int srcsize)
{
    asm volatile("cp.async.cg.shared.global [%0], [%1], 16, %2;"
                 :: "r"(dst), "l"(src), "r"(srcsize) : "memory");
}
__device__ __forceinline__ void cp_commit()
{
    asm volatile("cp.async.commit_group;" ::: "memory");
}
template<int NG>
__device__ __forceinline__ void cp_wait()
{
    asm volatile("cp.async.wait_group %0;" :: "n"(NG) : "memory");
}
__device__ __forceinline__ void ldsm_x4(u32 a, u32& r0, u32& r1, u32& r2, u32& r3)
{
    asm volatile("ldmatrix.sync.aligned.m8n8.x4.shared.b16 {%0,%1,%2,%3},[%4];"
                 : "=r"(r0), "=r"(r1), "=r"(r2), "=r"(r3) : "r"(a));
}
__device__ __forceinline__ void mma16816(float* c, u32 a0, u32 a1, u32 a2, u32 a3,
                                         u32 b0, u32 b1)
{
    asm volatile("mma.sync.aligned.m16n8k16.row.col.f32.bf16.bf16.f32 "
                 "{%0,%1,%2,%3},{%4,%5,%6,%7},{%8,%9},{%0,%1,%2,%3};"
                 : "+f"(c[0]), "+f"(c[1]), "+f"(c[2]), "+f"(c[3])
                 : "r"(a0), "r"(a1), "r"(a2), "r"(a3), "r"(b0), "r"(b1));
}

// ---------------- bf16x3 tensor-core GEMM (256 threads, 2 CTAs/SM) ----------------
#define GBM 128
#define GBN 128
#define GBK 32
#define BROW 40
#define ABUF (GBM * BROW)
#define GEMM_SMEM (8 * ABUF * 2)

__global__ void __launch_bounds__(256, 2)
k_gemm_bf3(const __nv_bfloat16* __restrict__ Ah, const __nv_bfloat16* __restrict__ Al,
           const __nv_bfloat16* __restrict__ Bh, const __nv_bfloat16* __restrict__ Bl,
           float* __restrict__ C, int M, int N, int K, const float* __restrict__ bias)
{
    extern __shared__ __nv_bfloat16 smg[];
    __nv_bfloat16* As = smg;
    __nv_bfloat16* Bs = smg + 4 * ABUF;
    const u32 sA = smem_u32(As);
    const u32 sB = smem_u32(Bs);

    const int tid  = threadIdx.x;
    const int bm   = blockIdx.y * GBM;
    const int bn   = blockIdx.x * GBN;
    const int warp = tid >> 5, lane = tid & 31;
    const int wm   = (warp >> 2) * 64;
    const int wn   = (warp & 3) * 32;

    float acc[4][4][4];
#pragma unroll
    for (int i = 0; i < 4; i++)
#pragma unroll
        for (int j = 0; j < 4; j++)
#pragma unroll
            for (int u = 0; u < 4; u++) acc[i][j][u] = 0.f;

    const int nstage = K / GBK;

    auto loadstage = [&](int kt, int st) {
        const int k0 = kt * GBK;
#pragma unroll
        for (int l = 0; l < 2; l++) {
            int i = tid + l * 256;
            int r = i >> 2, s = (i & 3) * 8;
            u32 doff = (u32)((r * BROW + s) * 2);
            size_t ga = (size_t)(bm + r) * K + k0 + s;
            cp16(sA + (u32)(st * 2 + 0) * (ABUF * 2) + doff, Ah + ga, 16);
            cp16(sA + (u32)(st * 2 + 1) * (ABUF * 2) + doff, Al + ga, 16);
            int nrow = bn + r;
            int ok = (nrow < N) ? 16 : 0;
            int nc = (nrow < N) ? nrow : (N - 1);
            size_t gb = (size_t)nc * K + k0 + s;
            cp16(sB + (u32)(st * 2 + 0) * (ABUF * 2) + doff, Bh + gb, ok);
            cp16(sB + (u32)(st * 2 + 1) * (ABUF * 2) + doff, Bl + gb, ok);
        }
        cp_commit();
    };

    loadstage(0, 0);
    int st = 0;
    for (int kt = 0; kt < nstage; kt++) {
        if (kt + 1 < nstage) { loadstage(kt + 1, st ^ 1); cp_wait<1>(); }
        else                 { cp_wait<0>(); }
        __syncthreads();

#pragma unroll
        for (int kk = 0; kk < 2; kk++) {
            u32 bfh[4][2], bfl[4][2];
#pragma unroll
            for (int half = 0; half < 2; half++) {
                int g = lane >> 3;
                u32 off = (u32)(((wn + half * 16 + (g & 1) * 8 + (lane & 7)) * BROW
                          + kk * 16 + (g >> 1) * 8) * 2);
                u32 r0, r1, r2, r3;
                ldsm_x4(sB + (u32)(st * 2 + 0) * (ABUF * 2) + off, r0, r1, r2, r3);
                bfh[half * 2 + 0][0] = r0; bfh[half * 2 + 1][0] = r1;
                bfh[half * 2 + 0][1] = r2; bfh[half * 2 + 1][1] = r3;
                ldsm_x4(sB + (u32)(st * 2 + 1) * (ABUF * 2) + off, r0, r1, r2, r3);
                bfl[half * 2 + 0][0] = r0; bfl[half * 2 + 1][0] = r1;
                bfl[half * 2 + 0][1] = r2; bfl[half * 2 + 1][1] = r3;
            }
#pragma unroll
            for (int mh = 0; mh < 2; mh++) {
                u32 afh[2][4], afl[2][4];
#pragma unroll
                for (int m2 = 0; m2 < 2; m2++) {
                    int mt = mh * 2 + m2;
                    u32 off = (u32)(((wm + mt * 16 + (lane & 15)) * BROW
                              + kk * 16 + (lane >> 4) * 8) * 2);
                    ldsm_x4(sA + (u32)(st * 2 + 0) * (ABUF * 2) + off,
                            afh[m2][0], afh[m2][1], afh[m2][2], afh[m2][3]);
                    ldsm_x4(sA + (u32)(st * 2 + 1) * (ABUF * 2) + off,
                            afl[m2][0], afl[m2][1], afl[m2][2], afl[m2][3]);
                }
#pragma unroll
                for (int m2 = 0; m2 < 2; m2++)
#pragma unroll
                    for (int nt = 0; nt < 4; nt++) {
                        float* a = acc[mh * 2 + m2][nt];
                        mma16816(a, afh[m2][0], afh[m2][1], afh[m2][2], afh[m2][3],
                                 bfh[nt][0], bfh[nt][1]);
                        mma16816(a, afh[m2][0], afh[m2][1], afh[m2][2], afh[m2][3],
                                 bfl[nt][0], bfl[nt][1]);
                        mma16816(a, afl[m2][0], afl[m2][1], afl[m2][2], afl[m2][3],
                                 bfh[nt][0], bfh[nt][1]);
                    }
            }
        }
        __syncthreads();
        st ^= 1;
    }

#pragma unroll
    for (int mt = 0; mt < 4; mt++) {
        int row0 = bm + wm + mt * 16 + (lane >> 2);
#pragma unroll
        for (int nt = 0; nt < 4; nt++) {
            int col = bn + wn + nt * 8 + (lane & 3) * 2;
            if (col < N) {
                float b0 = bias ? bias[col] : 0.f;
                float b1 = bias ? bias[col + 1] : 0.f;
                float2 v0 = make_float2(acc[mt][nt][0] + b0, acc[mt][nt][1] + b1);
                float2 v1 = make_float2(acc[mt][nt][2] + b0, acc[mt][nt][3] + b1);
                *reinterpret_cast<float2*>(&C[(size_t)row0 * N + col]) = v0;
                *reinterpret_cast<float2*>(&C[(size_t)(row0 + 8) * N + col]) = v1;
            }
        }
    }
}

// ---------------- split conversions ----------------
__global__ void k_split(const float* __restrict__ x, __nv_bfloat16* __restrict__ hi,
                        __nv_bfloat16* __restrict__ lo, int n)
{
    int i = blockIdx.x * blockDim.x + threadIdx.x;
    if (i < n) { __nv_bfloat16 h, l; split_bf16(x[i], h, l); hi[i] = h; lo[i] = l; }
}
__global__ void k_splitT(const float* __restrict__ W, __nv_bfloat16* __restrict__ hiT,
                         __nv_bfloat16* __restrict__ loT, int K, int N)
{
    __shared__ float tile[32][33];
    int k0 = blockIdx.y * 32, n0 = blockIdx.x * 32;
    int tx = threadIdx.x, ty = threadIdx.y;
    for (int i = ty; i < 32; i += 8)
        tile[i][tx] = W[(size_t)(k0 + i) * N + n0 + tx];
    __syncthreads();
    for (int i = ty; i < 32; i += 8) {
        float v = tile[tx][i];
        __nv_bfloat16 h, l; split_bf16(v, h, l);
        size_t o = (size_t)(n0 + i) * K + k0 + tx;
        hiT[o] = h; loT[o] = l;
    }
}

// ---------------- embedding gather + split ----------------
__global__ void k_gather_x0(const int* __restrict__ ids, const float* __restrict__ emb,
                            __nv_bfloat16* __restrict__ x0h, __nv_bfloat16* __restrict__ x0l)
{
    int i = blockIdx.x, t = threadIdx.x;
    int id = ids[i];
    float v = (id == 0) ? 0.f : emb[(size_t)id * Hd + t];
    __nv_bfloat16 h, l; split_bf16(v, h, l);
    x0h[(size_t)i * Hd + t] = h;
    x0l[(size_t)i * Hd + t] = l;
}

// ---------------- attention logits ----------------
__global__ void k_alpha1(const float* __restrict__ h1, const float* __restrict__ attS,
                         const float* __restrict__ attD,
                         float* __restrict__ outS, float* __restrict__ outD)
{
    int i = blockIdx.x;
    int w = threadIdx.x >> 5, lane = threadIdx.x & 31;
    const float* hp = h1 + (size_t)i * F1 + w * Hd;
    const float* ap = attS + w * Hd;
    const float* dp = attD + w * Hd;
    float ss = 0.f, sd = 0.f;
#pragma unroll
    for (int u = 0; u < 8; u++) {
        float v = hp[lane + 32 * u];
        ss += v * ap[lane + 32 * u];
        sd += v * dp[lane + 32 * u];
    }
#pragma unroll
    for (int o = 16; o; o >>= 1) {
        ss += __shfl_xor_sync(0xffffffffu, ss, o);
        sd += __shfl_xor_sync(0xffffffffu, sd, o);
    }
    if (lane == 0) { outS[i * NHEADS + w] = ss; outD[i * NHEADS + w] = sd; }
}

__global__ void k_alpha2(const float* __restrict__ h2, const float* __restrict__ attS,
                         const float* __restrict__ attD,
                         float* __restrict__ outS, float* __restrict__ outD)
{
    __shared__ float shS[8], shD[8];
    int i = blockIdx.x, t = threadIdx.x;
    float v = h2[(size_t)i * Hd + t];
    float ss = v * attS[t], sd = v * attD[t];
    int lane = t & 31, w = t >> 5;
#pragma unroll
    for (int o = 16; o; o >>= 1) {
        ss += __shfl_xor_sync(0xffffffffu, ss, o);
        sd += __shfl_xor_sync(0xffffffffu, sd, o);
    }
    if (lane == 0) { shS[w] = ss; shD[w] = sd; }
    __syncthreads();
    if (t == 0) {
        float a = 0.f, b = 0.f;
#pragma unroll
        for (int u = 0; u < 8; u++) { a += shS[u]; b += shD[u]; }
        outS[i] = a; outD[i] = b;
    }
}

// ---------------- CSR build ----------------
__global__ void k_init_counts(int* __restrict__ counts)
{
    int i = blockIdx.x * blockDim.x + threadIdx.x;
    if (i < Nn) counts[i] = 1;
}
__global__ void k_count_edges(const int* __restrict__ ei, int* __restrict__ counts)
{
    int e = blockIdx.x * blockDim.x + threadIdx.x;
    if (e < Ee) atomicAdd(&counts[ei[Ee + e]], 1);
}
__global__ void k_scan16k(const int* __restrict__ counts, int* __restrict__ rowptr,
                          int* __restrict__ cursor)
{
    __shared__ int wsum[32];
    const int tid = threadIdx.x;
    const int per = Nn / 1024;
    const int base = tid * per;
    int c[16];
    int tot = 0;
#pragma unroll
    for (int u = 0; u < per; u++) { c[u] = counts[base + u]; tot += c[u]; }
    int lane = tid & 31, wid = tid >> 5;
    int v = tot;
#pragma unroll
    for (int o = 1; o < 32; o <<= 1) {
        int t2 = __shfl_up_sync(0xffffffffu, v, o);
        if (lane >= o) v += t2;
    }
    if (lane == 31) wsum[wid] = v;
    __syncthreads();
    if (wid == 0) {
        int w = wsum[lane];
#pragma unroll
        for (int o = 1; o < 32; o <<= 1) {
            int t2 = __shfl_up_sync(0xffffffffu, w, o);
            if (lane >= o) w += t2;
        }
        wsum[lane] = w;
    }
    __syncthreads();
    int run = (v - tot) + (wid > 0 ? wsum[wid - 1] : 0);
#pragma unroll
    for (int u = 0; u < per; u++) {
        rowptr[base + u] = run;
        cursor[base + u] = run;
        run += c[u];
    }
    if (tid == 1023) rowptr[Nn] = run;
}
__global__ void k_scatter_edges(const int* __restrict__ ei,
                                int* __restrict__ cursor, int* __restrict__ colsrc)
{
    int e = blockIdx.x * blockDim.x + threadIdx.x;
    if (e < Ee) {
        int d = ei[Ee + e];
        int p = atomicAdd(&cursor[d], 1);
        colsrc[p] = ei[e];
    }
}
__global__ void k_scatter_loops(int* __restrict__ cursor, int* __restrict__ colsrc)
{
    int i = blockIdx.x * blockDim.x + threadIdx.x;
    if (i < Nn) {
        int p = atomicAdd(&cursor[i], 1);
        colsrc[p] = i;
    }
}

// ---------------- GAT aggregation: ONLINE softmax (single pass) ----------------
__global__ void k_gat1_agg(const float* __restrict__ h1,
                           const float* __restrict__ aS, const float* __restrict__ aD,
                           const int* __restrict__ rowptr, const int* __restrict__ colsrc,
                           const float* __restrict__ b1,
                           __nv_bfloat16* __restrict__ x1h, __nv_bfloat16* __restrict__ x1l)
{
    int dst = blockIdx.x;
    int w = threadIdx.x >> 5, lane = threadIdx.x & 31;
    int beg = rowptr[dst], end = rowptr[dst + 1];
    float adv = aD[dst * NHEADS + w];

    float m = -3.4e38f;
    float acc[8] = {0.f, 0.f, 0.f, 0.f, 0.f, 0.f, 0.f, 0.f};
    float sump = 0.f;
    for (int e = beg; e < end; e++) {
        int s = colsrc[e];
        float v = aS[s * NHEADS + w] + adv;
        v = v > 0.f ? v : 0.2f * v;
        float mn = fmaxf(m, v);
        float c  = expf(m - mn);   // 0 on first iteration (m = -inf-ish)
        float p  = expf(v - mn);
        m = mn;
        sump = sump * c + p;
        const float* hp = h1 + (size_t)s * F1 + w * Hd + lane;
#pragma unroll
        for (int u = 0; u < 8; u++) acc[u] = acc[u] * c + p * hp[u * 32];
    }
    float inv = 1.f / (sump + 1e-16f);
    size_t base = (size_t)dst * F1 + w * Hd + lane;
    const float* bp = b1 + w * Hd + lane;
#pragma unroll
    for (int u = 0; u < 8; u++) {
        float o = acc[u] * inv + bp[u * 32];
        o = o > 0.f ? o : expm1f(o);           // ELU
        __nv_bfloat16 h, l; split_bf16(o, h, l);
        x1h[base + u * 32] = h;
        x1l[base + u * 32] = l;
    }
}

__global__ void k_gat2_agg(const float* __restrict__ h2,
                           const float* __restrict__ aS, const float* __restrict__ aD,
                           const int* __restrict__ rowptr, const int* __restrict__ colsrc,
                           const float* __restrict__ b2,
                           __nv_bfloat16* __restrict__ o2h, __nv_bfloat16* __restrict__ o2l)
{
    int dst = blockIdx.x, t = threadIdx.x;
    int beg = rowptr[dst], end = rowptr[dst + 1];
    float adv = aD[dst];
    float m = -3.4e38f;
    float acc = 0.f, sump = 0.f;
    for (int e = beg; e < end; e++) {
        int s = colsrc[e];
        float v = aS[s] + adv;
        v = v > 0.f ? v : 0.2f * v;
        float mn = fmaxf(m, v);
        float c  = expf(m - mn);
        float p  = expf(v - mn);
        m = mn;
        sump = sump * c + p;
        acc = acc * c + p * h2[(size_t)s * Hd + t];
    }
    float o = acc / (sump + 1e-16f) + b2[t];
    __nv_bfloat16 h, l; split_bf16(o, h, l);
    o2h[(size_t)dst * Hd + t] = h;
    o2l[(size_t)dst * Hd + t] = l;
}

// ---------------- sequence bookkeeping ----------------
__global__ void k_init_misc(int* __restrict__ len, const float* __restrict__ bih,
                            const float* __restrict__ bhh, float* __restrict__ bs,
                            float* __restrict__ h)
{
    int i = blockIdx.x * blockDim.x + threadIdx.x;
    if (i < Bsz) len[i] = 0;
    if (i < G4) bs[i] = bih[i] + bhh[i];
    h[i] = 0.f;
}
__global__ void k_count_len(const int* __restrict__ batch, int* __restrict__ len)
{
    int i = blockIdx.x * blockDim.x + threadIdx.x;
    if (i < Nn) atomicAdd(&len[batch[i]], 1);
}
__global__ void k_scan256(const int* __restrict__ len, int* __restrict__ starts)
{
    __shared__ int wsum[8];
    int tid = threadIdx.x;
    int orig = len[tid];
    int v = orig;
    int lane = tid & 31, wid = tid >> 5;
#pragma unroll
    for (int o = 1; o < 32; o <<= 1) {
        int t2 = __shfl_up_sync(0xffffffffu, v, o);
        if (lane >= o) v += t2;
    }
    if (lane == 31) wsum[wid] = v;
    __syncthreads();
    if (tid == 0) {
        int s = 0;
#pragma unroll
        for (int u = 0; u < 8; u++) { int t2 = wsum[u]; wsum[u] = s; s += t2; }
    }
    __syncthreads();
    starts[tid] = (v - orig) + wsum[wid];
}
__global__ void k_nodeidx(const int* __restrict__ batch, const int* __restrict__ starts,
                          int* __restrict__ nodeidx)
{
    int i = blockIdx.x * blockDim.x + threadIdx.x;
    if (i < Nn) {
        int b = batch[i];
        int p = i - starts[b];
        if (p >= 0 && p < Lseq) nodeidx[b * Lseq + p] = i;
    }
}

// ---------------- persistent fused LSTM (8x8 thread tile, ksplit=8) ----------------
// block: jb (16 hidden-unit slice) x mb (32-batch tile). WshT [256 k][64 rows] str 68.
// HshT [256 k][32 batch] str 36 (float4-aligned). red [8 q][64 rows][32 batch] str 33.
// thread: kg = tid>>5 (8 groups of 32 k each); rowq = tid&7 (8 rows), bq = (tid>>3)&3 (8 batches).
#define WST 68
#define HST 36
__global__ void __launch_bounds__(256, 1)
k_lstm(const float* __restrict__ xg, const int* __restrict__ nodeidx,
       const int* __restrict__ len, float* __restrict__ hbuf0,
       float* __restrict__ hbuf1, const float* __restrict__ Whh)
{
    extern __shared__ float sm[];
    float* WshT = sm;                       // 256*68
    float* HshT = sm + 256 * WST;           // 256*36
    float* red  = HshT + 256 * HST;         // 8*64*33
    float* csh  = red + 8 * 64 * 33;        // 512

    const int tid  = threadIdx.x;
    const int jb   = blockIdx.x & 15;
    const int mb   = blockIdx.x >> 4;
    const int kg   = tid >> 5;              // 0..7
    const int rowq = tid & 7;               // rows rowq*8..+8
    const int bq   = (tid >> 3) & 3;        // batches bq*8..+8

    unsigned my_gen = atomicAdd(&g_bar_gen, 0u);

    // Whh slice transposed: local row r = g*16+u <-> global row g*256 + jb*16 + u
    for (int idx = tid; idx < 64 * 256; idx += 256) {
        int r = idx >> 8;
        int k = idx & 255;
        int g = r >> 4, u = r & 15;
        WshT[k * WST + r] = Whh[(size_t)(g * 256 + jb * 16 + u) * 256 + k];
    }
    if (tid < 256) { csh[tid] = 0.f; csh[tid + 256] = 0.f; }

    for (int t = 0; t < Lseq; t++) {
        const float* hc = (t & 1) ? hbuf1 : hbuf0;
#pragma unroll
        for (int l = 0; l < 32; l++) {
            int idx = tid + l * 256;
            int bl = idx >> 8, k = idx & 255;
            HshT[k * HST + bl] = __ldcg(&hc[(mb * 32 + bl) * 256 + k]);
        }
        __syncthreads();

        // ---- 8x8 tile GEMM over k-range [kg*32, kg*32+32) ----
        float acc[8][8];
#pragma unroll
        for (int i = 0; i < 8; i++)
#pragma unroll
            for (int j = 0; j < 8; j++) acc[i][j] = 0.f;
        const int k0 = kg * 32;
#pragma unroll 4
        for (int k = k0; k < k0 + 32; k++) {
            float4 w0 = *reinterpret_cast<const float4*>(&WshT[k * WST + rowq * 8]);
            float4 w1 = *reinterpret_cast<const float4*>(&WshT[k * WST + rowq * 8 + 4]);
            float4 h0 = *reinterpret_cast<const float4*>(&HshT[k * HST + bq * 8]);
            float4 h1 = *reinterpret_cast<const float4*>(&HshT[k * HST + bq * 8 + 4]);
            float wv[8] = {w0.x, w0.y, w0.z, w0.w, w1.x, w1.y, w1.z, w1.w};
            float hv[8] = {h0.x, h0.y, h0.z, h0.w, h1.x, h1.y, h1.z, h1.w};
#pragma unroll
            for (int i = 0; i < 8; i++)
#pragma unroll
                for (int j = 0; j < 8; j++) acc[i][j] += wv[i] * hv[j];
        }
#pragma unroll
        for (int i = 0; i < 8; i++)
#pragma unroll
            for (int j = 0; j < 8; j++)
                red[kg * (64 * 33) + (rowq * 8 + i) * 33 + bq * 8 + j] = acc[i][j];
        __syncthreads();

        // ---- combine 8 partials + xg, gates, update c (smem) & h (global) ----
        float* hn_buf = (t & 1) ? hbuf0 : hbuf1;
#pragma unroll
        for (int p = tid; p < 512; p += 256) {
            int u = p & 15;
            int bl = p >> 4;
            int bglob = mb * 32 + bl;
            int node = nodeidx[bglob * Lseq + t];
            const float* xp = xg + (size_t)node * G4 + jb * 16 + u;
            float gi = 0.f, gf = 0.f, gg = 0.f, go = 0.f;
#pragma unroll
            for (int q = 0; q < 8; q++) {
                const float* rq = red + q * (64 * 33);
                gi += rq[(0 * 16 + u) * 33 + bl];
                gf += rq[(1 * 16 + u) * 33 + bl];
                gg += rq[(2 * 16 + u) * 33 + bl];
                go += rq[(3 * 16 + u) * 33 + bl];
            }
            gi += xp[0]; gf += xp[256]; gg += xp[512]; go += xp[768];
            float hprev = HshT[(jb * 16 + u) * HST + bl];
            float cprev = csh[u * 32 + bl];
            float si = 1.f / (1.f + expf(-gi));
            float sf = 1.f / (1.f + expf(-gf));
            float so = 1.f / (1.f + expf(-go));
            float cn = sf * cprev + si * tanhf(gg);
            float hn = so * tanhf(cn);
            bool act = (t < len[bglob]);
            if (act) csh[u * 32 + bl] = cn;
            float hw = act ? hn : hprev;
            __stcg(&hn_buf[bglob * 256 + jb * 16 + u], hw);
        }

        if (t != Lseq - 1) {
            __threadfence();
            __syncthreads();
            if (tid == 0) {
                unsigned old = atomicAdd(&g_bar_arrive, 1u);
                if (old == LSTM_BLOCKS - 1) {
                    atomicExch(&g_bar_arrive, 0u);
                    __threadfence();
                    atomicAdd(&g_bar_gen, 1u);
                } else {
                    while (atomicAdd(&g_bar_gen, 0u) == my_gen) __nanosleep(64);
                }
            }
            __syncthreads();
            my_gen++;
        }
    }
}

// ---------------- host launcher ----------------
extern "C" void kernel_launch(void* const* d_in, const int* in_sizes, int n_in,
                              void* d_out, int out_size)
{
    const int*   x_ids = (const int*)d_in[0];
    const int*   ei    = (const int*)d_in[1];
    const int*   batch = (const int*)d_in[2];
    const float* emb   = (const float*)d_in[3];
    const float* W1    = (const float*)d_in[4];
    const float* attS1 = (const float*)d_in[5];
    const float* attD1 = (const float*)d_in[6];
    const float* b1    = (const float*)d_in[7];
    const float* W2    = (const float*)d_in[8];
    const float* attS2 = (const float*)d_in[9];
    const float* attD2 = (const float*)d_in[10];
    const float* b2    = (const float*)d_in[11];
    const float* Wih   = (const float*)d_in[12];
    const float* Whh   = (const float*)d_in[13];
    const float* bih   = (const float*)d_in[14];
    const float* bhh   = (const float*)d_in[15];
    const float* Wp    = (const float*)d_in[16];
    const float* bp    = (const float*)d_in[17];
    float* out = (float*)d_out;

    void* p;
    cudaGetSymbolAddress(&p, g_h1);      float* h1   = (float*)p;
    cudaGetSymbolAddress(&p, g_h2);      float* h2   = (float*)p;
    cudaGetSymbolAddress(&p, g_xg);      float* xg   = (float*)p;
    cudaGetSymbolAddress(&p, g_as1);     float* as1  = (float*)p;
    cudaGetSymbolAddress(&p, g_ad1);     float* ad1  = (float*)p;
    cudaGetSymbolAddress(&p, g_as2);     float* as2  = (float*)p;
    cudaGetSymbolAddress(&p, g_ad2);     float* ad2  = (float*)p;
    cudaGetSymbolAddress(&p, g_counts);  int* counts = (int*)p;
    cudaGetSymbolAddress(&p, g_rowptr);  int* rowptr = (int*)p;
    cudaGetSymbolAddress(&p, g_cursor);  int* cursor = (int*)p;
    cudaGetSymbolAddress(&p, g_colsrc);  int* colsrc = (int*)p;
    cudaGetSymbolAddress(&p, g_len);     int* len    = (int*)p;
    cudaGetSymbolAddress(&p, g_starts);  int* starts = (int*)p;
    cudaGetSymbolAddress(&p, g_nodeidx); int* nodeidx= (int*)p;
    cudaGetSymbolAddress(&p, g_hbuf1);   float* hb1  = (float*)p;
    cudaGetSymbolAddress(&p, g_h);       float* hS   = (float*)p;
    cudaGetSymbolAddress(&p, g_bsum);    float* bsum = (float*)p;

    __nv_bfloat16 *x0h, *x0l, *x1h, *x1l, *o2h, *o2l;
    __nv_bfloat16 *W1Th, *W1Tl, *W2Th, *W2Tl, *Wihh, *Wihl, *hTh, *hTl, *Wph, *Wpl;
    cudaGetSymbolAddress(&p, g_x0h); x0h = (__nv_bfloat16*)p;
    cudaGetSymbolAddress(&p, g_x0l); x0l = (__nv_bfloat16*)p;
    cudaGetSymbolAddress(&p, g_x1h); x1h = (__nv_bfloat16*)p;
    cudaGetSymbolAddress(&p, g_x1l); x1l = (__nv_bfloat16*)p;
    cudaGetSymbolAddress(&p, g_o2h); o2h = (__nv_bfloat16*)p;
    cudaGetSymbolAddress(&p, g_o2l); o2l = (__nv_bfloat16*)p;
    cudaGetSymbolAddress(&p, g_W1Th); W1Th = (__nv_bfloat16*)p;
    cudaGetSymbolAddress(&p, g_W1Tl); W1Tl = (__nv_bfloat16*)p;
    cudaGetSymbolAddress(&p, g_W2Th); W2Th = (__nv_bfloat16*)p;
    cudaGetSymbolAddress(&p, g_W2Tl); W2Tl = (__nv_bfloat16*)p;
    cudaGetSymbolAddress(&p, g_Wihh); Wihh = (__nv_bfloat16*)p;
    cudaGetSymbolAddress(&p, g_Wihl); Wihl = (__nv_bfloat16*)p;
    cudaGetSymbolAddress(&p, g_hTh);  hTh  = (__nv_bfloat16*)p;
    cudaGetSymbolAddress(&p, g_hTl);  hTl  = (__nv_bfloat16*)p;
    cudaGetSymbolAddress(&p, g_Wph);  Wph  = (__nv_bfloat16*)p;
    cudaGetSymbolAddress(&p, g_Wpl);  Wpl  = (__nv_bfloat16*)p;

    static const int LSTM_SMEM = (256 * WST + 256 * HST + 8 * 64 * 33 + 512) * 4;
    cudaFuncSetAttribute(k_lstm, cudaFuncAttributeMaxDynamicSharedMemorySize, LSTM_SMEM);
    cudaFuncSetAttribute(k_gemm_bf3, cudaFuncAttributeMaxDynamicSharedMemorySize, GEMM_SMEM);

    // launch #1-#4 arranged so the ncu-profiled slot (#4) is GEMM1
    k_gather_x0<<<Nn, Hd>>>(x_ids, emb, x0h, x0l);                            // 1
    k_splitT<<<dim3(F1 / 32, Hd / 32), dim3(32, 8)>>>(W1, W1Th, W1Tl, Hd, F1); // 2
    k_init_counts<<<Nn / 256, 256>>>(counts);                                 // 3
    k_gemm_bf3<<<dim3(F1 / GBN, Nn / GBM), 256, GEMM_SMEM>>>(                 // 4 (profiled)
        x0h, x0l, W1Th, W1Tl, h1, Nn, F1, Hd, nullptr);

    // remaining weight conversions
    k_splitT<<<dim3(Hd / 32, F1 / 32), dim3(32, 8)>>>(W2, W2Th, W2Tl, F1, Hd);
    k_split<<<(G4 * Hd + 255) / 256, 256>>>(Wih, Wihh, Wihl, G4 * Hd);
    k_split<<<(NNODE_ * Hd + 255) / 256, 256>>>(Wp, Wph, Wpl, NNODE_ * Hd);

    // attention logits (layer 1)
    k_alpha1<<<Nn, 256>>>(h1, attS1, attD1, as1, ad1);

    // CSR by dst
    k_count_edges<<<Ee / 256, 256>>>(ei, counts);
    k_scan16k<<<1, 1024>>>(counts, rowptr, cursor);
    k_scatter_edges<<<Ee / 256, 256>>>(ei, cursor, colsrc);
    k_scatter_loops<<<Nn / 256, 256>>>(cursor, colsrc);

    // GAT1 aggregate (online softmax) + b1 + ELU -> x1 (bf16 split fused)
    k_gat1_agg<<<Nn, 256>>>(h1, as1, ad1, rowptr, colsrc, b1, x1h, x1l);

    // h2 = x1 @ W2
    k_gemm_bf3<<<dim3(Hd / GBN, Nn / GBM), 256, GEMM_SMEM>>>(
        x1h, x1l, W2Th, W2Tl, h2, Nn, Hd, F1, nullptr);

    // layer-2 logits
    k_alpha2<<<Nn, 256>>>(h2, attS2, attD2, as2, ad2);

    // GAT2 aggregate (online softmax) + b2 -> out2 (bf16 split fused)
    k_gat2_agg<<<Nn, 256>>>(h2, as2, ad2, rowptr, colsrc, b2, o2h, o2l);

    // sequence bookkeeping
    k_init_misc<<<(Bsz * Hd) / 256, 256>>>(len, bih, bhh, bsum, hS);
    k_count_len<<<Nn / 256, 256>>>(batch, len);
    k_scan256<<<1, Bsz>>>(len, starts);
    k_nodeidx<<<Nn / 256, 256>>>(batch, starts, nodeidx);

    // xg = out2 @ Wih^T + (bih + bhh)
    k_gemm_bf3<<<dim3(G4 / GBN, Nn / GBM), 256, GEMM_SMEM>>>(
        o2h, o2l, Wihh, Wihl, xg, Nn, G4, Hd, bsum);

    // persistent fused LSTM
    k_lstm<<<LSTM_BLOCKS, 256, LSTM_SMEM>>>(xg, nodeidx, len, hS, hb1, Whh);

    // out = hT @ Wp^T + bp
    k_split<<<(Bsz * Hd + 255) / 256, 256>>>(hS, hTh, hTl, Bsz * Hd);
    k_gemm_bf3<<<dim3((NNODE_ + GBN - 1) / GBN, Bsz / GBM), 256, GEMM_SMEM>>>(
        hTh, hTl, Wph, Wpl, out, Bsz, NNODE_, Hd, bp);
}

// round 12
// speedup vs baseline: 1.0343x; 1.0343x over previous
#include <cuda_runtime.h>
#include <cuda_bf16.h>
#include <stdint.h>
#include <math.h>

typedef unsigned int u32;

// ---------------- problem constants ----------------
#define Nn      16384
#define Ee      131072
#define ETOT    (Ee + Nn)
#define Bsz     256
#define Lseq    64
#define Hd      256
#define NHEADS  8
#define F1      2048
#define G4      1024
#define NNODE_  37000

#define LSTM_BLOCKS 128

// ---------------- device scratch ----------------
__device__ float g_h1  [(size_t)Nn * F1];
__device__ float g_h2  [(size_t)Nn * Hd];
__device__ float g_xg  [(size_t)Nn * G4];
__device__ float g_as1 [Nn * NHEADS];
__device__ float g_ad1 [Nn * NHEADS];
__device__ float g_as2 [Nn];
__device__ float g_ad2 [Nn];
__device__ int   g_counts[Nn];
__device__ int   g_rowptr[Nn + 1];
__device__ int   g_cursor[Nn];
__device__ int   g_colsrc[ETOT];
__device__ int   g_len   [Bsz];
__device__ int   g_starts[Bsz];
__device__ int   g_nodeidx[Bsz * Lseq];
__device__ float g_hbuf1[Bsz * Hd];
__device__ float g_h    [Bsz * Hd];
__device__ float g_bsum [G4];
__device__ unsigned g_bar_arrive = 0;
__device__ unsigned g_bar_gen    = 0;

// bf16 hi/lo split operands for tensor-core GEMMs
__device__ __nv_bfloat16 g_x0h[(size_t)Nn * Hd],  g_x0l[(size_t)Nn * Hd];
__device__ __nv_bfloat16 g_x1h[(size_t)Nn * F1],  g_x1l[(size_t)Nn * F1];
__device__ __nv_bfloat16 g_o2h[(size_t)Nn * Hd],  g_o2l[(size_t)Nn * Hd];
__device__ __nv_bfloat16 g_W1Th[(size_t)F1 * Hd], g_W1Tl[(size_t)F1 * Hd];
__device__ __nv_bfloat16 g_W2Th[(size_t)Hd * F1], g_W2Tl[(size_t)Hd * F1];
__device__ __nv_bfloat16 g_Wihh[(size_t)G4 * Hd], g_Wihl[(size_t)G4 * Hd];
__device__ __nv_bfloat16 g_hTh[Bsz * Hd],         g_hTl[Bsz * Hd];
__device__ __nv_bfloat16 g_Wph[(size_t)NNODE_ * Hd], g_Wpl[(size_t)NNODE_ * Hd];

// ---------------- small helpers ----------------
__device__ __forceinline__ void split_bf16(float v, __nv_bfloat16& h, __nv_bfloat16& l)
{
    h = __float2bfloat16(v);
    l = __float2bfloat16(v - __bfloat162float(h));
}
__device__ __forceinline__ u32 smem_u32(const void* p)
{
    return (u32)__cvta_generic_to_shared(p);
}
__device__ __forceinline__ void cp16(u32 dst, const void* src, int srcsize)
{
    asm volatile("cp.async.cg.shared.global [%0], [%1], 16, %2;"
                 :: "r"(dst), "l"(src), "r"(srcsize) : "memory");
}
__device__ __forceinline__ void cp_commit()
{
    asm volatile("cp.async.commit_group;" ::: "memory");
}
template<int NG>
__device__ __forceinline__ void cp_wait()
{
    asm volatile("cp.async.wait_group %0;" :: "n"(NG) : "memory");
}
__device__ __forceinline__ void ldsm_x4(u32 a, u32& r0, u32& r1, u32& r2, u32& r3)
{
    asm volatile("ldmatrix.sync.aligned.m8n8.x4.shared.b16 {%0,%1,%2,%3},[%4];"
                 : "=r"(r0), "=r"(r1), "=r"(r2), "=r"(r3) : "r"(a));
}
__device__ __forceinline__ void mma16816(float* c, u32 a0, u32 a1, u32 a2, u32 a3,
                                         u32 b0, u32 b1)
{
    asm volatile("mma.sync.aligned.m16n8k16.row.col.f32.bf16.bf16.f32 "
                 "{%0,%1,%2,%3},{%4,%5,%6,%7},{%8,%9},{%0,%1,%2,%3};"
                 : "+f"(c[0]), "+f"(c[1]), "+f"(c[2]), "+f"(c[3])
                 : "r"(a0), "r"(a1), "r"(a2), "r"(a3), "r"(b0), "r"(b1));
}

// ---------------- bf16x3 tensor-core GEMM (256 threads, 2 CTAs/SM) ----------------
#define GBM 128
#define GBN 128
#define GBK 32
#define BROW 40
#define ABUF (GBM * BROW)
#define GEMM_SMEM (8 * ABUF * 2)

__global__ void __launch_bounds__(256, 2)
k_gemm_bf3(const __nv_bfloat16* __restrict__ Ah, const __nv_bfloat16* __restrict__ Al,
           const __nv_bfloat16* __restrict__ Bh, const __nv_bfloat16* __restrict__ Bl,
           float* __restrict__ C, int M, int N, int K, const float* __restrict__ bias)
{
    extern __shared__ __nv_bfloat16 smg[];
    __nv_bfloat16* As = smg;
    __nv_bfloat16* Bs = smg + 4 * ABUF;
    const u32 sA = smem_u32(As);
    const u32 sB = smem_u32(Bs);

    const int tid  = threadIdx.x;
    const int bm   = blockIdx.y * GBM;
    const int bn   = blockIdx.x * GBN;
    const int warp = tid >> 5, lane = tid & 31;
    const int wm   = (warp >> 2) * 64;
    const int wn   = (warp & 3) * 32;

    float acc[4][4][4];
#pragma unroll
    for (int i = 0; i < 4; i++)
#pragma unroll
        for (int j = 0; j < 4; j++)
#pragma unroll
            for (int u = 0; u < 4; u++) acc[i][j][u] = 0.f;

    const int nstage = K / GBK;

    auto loadstage = [&](int kt, int st) {
        const int k0 = kt * GBK;
#pragma unroll
        for (int l = 0; l < 2; l++) {
            int i = tid + l * 256;
            int r = i >> 2, s = (i & 3) * 8;
            u32 doff = (u32)((r * BROW + s) * 2);
            size_t ga = (size_t)(bm + r) * K + k0 + s;
            cp16(sA + (u32)(st * 2 + 0) * (ABUF * 2) + doff, Ah + ga, 16);
            cp16(sA + (u32)(st * 2 + 1) * (ABUF * 2) + doff, Al + ga, 16);
            int nrow = bn + r;
            int ok = (nrow < N) ? 16 : 0;
            int nc = (nrow < N) ? nrow : (N - 1);
            size_t gb = (size_t)nc * K + k0 + s;
            cp16(sB + (u32)(st * 2 + 0) * (ABUF * 2) + doff, Bh + gb, ok);
            cp16(sB + (u32)(st * 2 + 1) * (ABUF * 2) + doff, Bl + gb, ok);
        }
        cp_commit();
    };

    loadstage(0, 0);
    int st = 0;
    for (int kt = 0; kt < nstage; kt++) {
        if (kt + 1 < nstage) { loadstage(kt + 1, st ^ 1); cp_wait<1>(); }
        else                 { cp_wait<0>(); }
        __syncthreads();

#pragma unroll
        for (int kk = 0; kk < 2; kk++) {
            u32 bfh[4][2], bfl[4][2];
#pragma unroll
            for (int half = 0; half < 2; half++) {
                int g = lane >> 3;
                u32 off = (u32)(((wn + half * 16 + (g & 1) * 8 + (lane & 7)) * BROW
                          + kk * 16 + (g >> 1) * 8) * 2);
                u32 r0, r1, r2, r3;
                ldsm_x4(sB + (u32)(st * 2 + 0) * (ABUF * 2) + off, r0, r1, r2, r3);
                bfh[half * 2 + 0][0] = r0; bfh[half * 2 + 1][0] = r1;
                bfh[half * 2 + 0][1] = r2; bfh[half * 2 + 1][1] = r3;
                ldsm_x4(sB + (u32)(st * 2 + 1) * (ABUF * 2) + off, r0, r1, r2, r3);
                bfl[half * 2 + 0][0] = r0; bfl[half * 2 + 1][0] = r1;
                bfl[half * 2 + 0][1] = r2; bfl[half * 2 + 1][1] = r3;
            }
#pragma unroll
            for (int mh = 0; mh < 2; mh++) {
                u32 afh[2][4], afl[2][4];
#pragma unroll
                for (int m2 = 0; m2 < 2; m2++) {
                    int mt = mh * 2 + m2;
                    u32 off = (u32)(((wm + mt * 16 + (lane & 15)) * BROW
                              + kk * 16 + (lane >> 4) * 8) * 2);
                    ldsm_x4(sA + (u32)(st * 2 + 0) * (ABUF * 2) + off,
                            afh[m2][0], afh[m2][1], afh[m2][2], afh[m2][3]);
                    ldsm_x4(sA + (u32)(st * 2 + 1) * (ABUF * 2) + off,
                            afl[m2][0], afl[m2][1], afl[m2][2], afl[m2][3]);
                }
#pragma unroll
                for (int m2 = 0; m2 < 2; m2++)
#pragma unroll
                    for (int nt = 0; nt < 4; nt++) {
                        float* a = acc[mh * 2 + m2][nt];
                        mma16816(a, afh[m2][0], afh[m2][1], afh[m2][2], afh[m2][3],
                                 bfh[nt][0], bfh[nt][1]);
                        mma16816(a, afh[m2][0], afh[m2][1], afh[m2][2], afh[m2][3],
                                 bfl[nt][0], bfl[nt][1]);
                        mma16816(a, afl[m2][0], afl[m2][1], afl[m2][2], afl[m2][3],
                                 bfh[nt][0], bfh[nt][1]);
                    }
            }
        }
        __syncthreads();
        st ^= 1;
    }

#pragma unroll
    for (int mt = 0; mt < 4; mt++) {
        int row0 = bm + wm + mt * 16 + (lane >> 2);
#pragma unroll
        for (int nt = 0; nt < 4; nt++) {
            int col = bn + wn + nt * 8 + (lane & 3) * 2;
            if (col < N) {
                float b0 = bias ? bias[col] : 0.f;
                float b1 = bias ? bias[col + 1] : 0.f;
                float2 v0 = make_float2(acc[mt][nt][0] + b0, acc[mt][nt][1] + b1);
                float2 v1 = make_float2(acc[mt][nt][2] + b0, acc[mt][nt][3] + b1);
                *reinterpret_cast<float2*>(&C[(size_t)row0 * N + col]) = v0;
                *reinterpret_cast<float2*>(&C[(size_t)(row0 + 8) * N + col]) = v1;
            }
        }
    }
}

// ---------------- split conversions ----------------
__global__ void k_split(const float* __restrict__ x, __nv_bfloat16* __restrict__ hi,
                        __nv_bfloat16* __restrict__ lo, int n)
{
    int i = blockIdx.x * blockDim.x + threadIdx.x;
    if (i < n) { __nv_bfloat16 h, l; split_bf16(x[i], h, l); hi[i] = h; lo[i] = l; }
}
__global__ void k_splitT(const float* __restrict__ W, __nv_bfloat16* __restrict__ hiT,
                         __nv_bfloat16* __restrict__ loT, int K, int N)
{
    __shared__ float tile[32][33];
    int k0 = blockIdx.y * 32, n0 = blockIdx.x * 32;
    int tx = threadIdx.x, ty = threadIdx.y;
    for (int i = ty; i < 32; i += 8)
        tile[i][tx] = W[(size_t)(k0 + i) * N + n0 + tx];
    __syncthreads();
    for (int i = ty; i < 32; i += 8) {
        float v = tile[tx][i];
        __nv_bfloat16 h, l; split_bf16(v, h, l);
        size_t o = (size_t)(n0 + i) * K + k0 + tx;
        hiT[o] = h; loT[o] = l;
    }
}

// ---------------- embedding gather + split ----------------
__global__ void k_gather_x0(const int* __restrict__ ids, const float* __restrict__ emb,
                            __nv_bfloat16* __restrict__ x0h, __nv_bfloat16* __restrict__ x0l)
{
    int i = blockIdx.x, t = threadIdx.x;
    int id = ids[i];
    float v = (id == 0) ? 0.f : emb[(size_t)id * Hd + t];
    __nv_bfloat16 h, l; split_bf16(v, h, l);
    x0h[(size_t)i * Hd + t] = h;
    x0l[(size_t)i * Hd + t] = l;
}

// ---------------- attention logits ----------------
__global__ void k_alpha1(const float* __restrict__ h1, const float* __restrict__ attS,
                         const float* __restrict__ attD,
                         float* __restrict__ outS, float* __restrict__ outD)
{
    int i = blockIdx.x;
    int w = threadIdx.x >> 5, lane = threadIdx.x & 31;
    const float* hp = h1 + (size_t)i * F1 + w * Hd;
    const float* ap = attS + w * Hd;
    const float* dp = attD + w * Hd;
    float ss = 0.f, sd = 0.f;
#pragma unroll
    for (int u = 0; u < 8; u++) {
        float v = hp[lane + 32 * u];
        ss += v * ap[lane + 32 * u];
        sd += v * dp[lane + 32 * u];
    }
#pragma unroll
    for (int o = 16; o; o >>= 1) {
        ss += __shfl_xor_sync(0xffffffffu, ss, o);
        sd += __shfl_xor_sync(0xffffffffu, sd, o);
    }
    if (lane == 0) { outS[i * NHEADS + w] = ss; outD[i * NHEADS + w] = sd; }
}

__global__ void k_alpha2(const float* __restrict__ h2, const float* __restrict__ attS,
                         const float* __restrict__ attD,
                         float* __restrict__ outS, float* __restrict__ outD)
{
    __shared__ float shS[8], shD[8];
    int i = blockIdx.x, t = threadIdx.x;
    float v = h2[(size_t)i * Hd + t];
    float ss = v * attS[t], sd = v * attD[t];
    int lane = t & 31, w = t >> 5;
#pragma unroll
    for (int o = 16; o; o >>= 1) {
        ss += __shfl_xor_sync(0xffffffffu, ss, o);
        sd += __shfl_xor_sync(0xffffffffu, sd, o);
    }
    if (lane == 0) { shS[w] = ss; shD[w] = sd; }
    __syncthreads();
    if (t == 0) {
        float a = 0.f, b = 0.f;
#pragma unroll
        for (int u = 0; u < 8; u++) { a += shS[u]; b += shD[u]; }
        outS[i] = a; outD[i] = b;
    }
}

// ---------------- CSR build ----------------
__global__ void k_init_counts(int* __restrict__ counts)
{
    int i = blockIdx.x * blockDim.x + threadIdx.x;
    if (i < Nn) counts[i] = 1;
}
__global__ void k_count_edges(const int* __restrict__ ei, int* __restrict__ counts)
{
    int e = blockIdx.x * blockDim.x + threadIdx.x;
    if (e < Ee) atomicAdd(&counts[ei[Ee + e]], 1);
}
__global__ void k_scan16k(const int* __restrict__ counts, int* __restrict__ rowptr,
                          int* __restrict__ cursor)
{
    __shared__ int wsum[32];
    const int tid = threadIdx.x;
    const int per = Nn / 1024;
    const int base = tid * per;
    int c[16];
    int tot = 0;
#pragma unroll
    for (int u = 0; u < per; u++) { c[u] = counts[base + u]; tot += c[u]; }
    int lane = tid & 31, wid = tid >> 5;
    int v = tot;
#pragma unroll
    for (int o = 1; o < 32; o <<= 1) {
        int t2 = __shfl_up_sync(0xffffffffu, v, o);
        if (lane >= o) v += t2;
    }
    if (lane == 31) wsum[wid] = v;
    __syncthreads();
    if (wid == 0) {
        int w = wsum[lane];
#pragma unroll
        for (int o = 1; o < 32; o <<= 1) {
            int t2 = __shfl_up_sync(0xffffffffu, w, o);
            if (lane >= o) w += t2;
        }
        wsum[lane] = w;
    }
    __syncthreads();
    int run = (v - tot) + (wid > 0 ? wsum[wid - 1] : 0);
#pragma unroll
    for (int u = 0; u < per; u++) {
        rowptr[base + u] = run;
        cursor[base + u] = run;
        run += c[u];
    }
    if (tid == 1023) rowptr[Nn] = run;
}
__global__ void k_scatter_edges(const int* __restrict__ ei,
                                int* __restrict__ cursor, int* __restrict__ colsrc)
{
    int e = blockIdx.x * blockDim.x + threadIdx.x;
    if (e < Ee) {
        int d = ei[Ee + e];
        int p = atomicAdd(&cursor[d], 1);
        colsrc[p] = ei[e];
    }
}
__global__ void k_scatter_loops(int* __restrict__ cursor, int* __restrict__ colsrc)
{
    int i = blockIdx.x * blockDim.x + threadIdx.x;
    if (i < Nn) {
        int p = atomicAdd(&cursor[i], 1);
        colsrc[p] = i;
    }
}

// ---------------- GAT aggregation (two-pass softmax, fused bf16 split) ----------------
__global__ void k_gat1_agg(const float* __restrict__ h1,
                           const float* __restrict__ aS, const float* __restrict__ aD,
                           const int* __restrict__ rowptr, const int* __restrict__ colsrc,
                           const float* __restrict__ b1,
                           __nv_bfloat16* __restrict__ x1h, __nv_bfloat16* __restrict__ x1l)
{
    int dst = blockIdx.x;
    int w = threadIdx.x >> 5, lane = threadIdx.x & 31;
    int beg = rowptr[dst], end = rowptr[dst + 1];
    float adv = aD[dst * NHEADS + w];

    float m = -3.4e38f;
    for (int e = beg; e < end; e++) {
        float v = aS[colsrc[e] * NHEADS + w] + adv;
        v = v > 0.f ? v : 0.2f * v;
        m = fmaxf(m, v);
    }
    float acc[8] = {0.f, 0.f, 0.f, 0.f, 0.f, 0.f, 0.f, 0.f};
    float sump = 0.f;
    for (int e = beg; e < end; e++) {
        int s = colsrc[e];
        float v = aS[s * NHEADS + w] + adv;
        v = v > 0.f ? v : 0.2f * v;
        float p = expf(v - m);
        sump += p;
        const float* hp = h1 + (size_t)s * F1 + w * Hd + lane;
#pragma unroll
        for (int u = 0; u < 8; u++) acc[u] += p * hp[u * 32];
    }
    float inv = 1.f / (sump + 1e-16f);
    size_t base = (size_t)dst * F1 + w * Hd + lane;
    const float* bp = b1 + w * Hd + lane;
#pragma unroll
    for (int u = 0; u < 8; u++) {
        float o = acc[u] * inv + bp[u * 32];
        o = o > 0.f ? o : expm1f(o);           // ELU
        __nv_bfloat16 h, l; split_bf16(o, h, l);
        x1h[base + u * 32] = h;
        x1l[base + u * 32] = l;
    }
}

__global__ void k_gat2_agg(const float* __restrict__ h2,
                           const float* __restrict__ aS, const float* __restrict__ aD,
                           const int* __restrict__ rowptr, const int* __restrict__ colsrc,
                           const float* __restrict__ b2,
                           __nv_bfloat16* __restrict__ o2h, __nv_bfloat16* __restrict__ o2l)
{
    int dst = blockIdx.x, t = threadIdx.x;
    int beg = rowptr[dst], end = rowptr[dst + 1];
    float adv = aD[dst];
    float m = -3.4e38f;
    for (int e = beg; e < end; e++) {
        float v = aS[colsrc[e]] + adv;
        v = v > 0.f ? v : 0.2f * v;
        m = fmaxf(m, v);
    }
    float acc = 0.f, sump = 0.f;
    for (int e = beg; e < end; e++) {
        int s = colsrc[e];
        float v = aS[s] + adv;
        v = v > 0.f ? v : 0.2f * v;
        float p = expf(v - m);
        sump += p;
        acc += p * h2[(size_t)s * Hd + t];
    }
    float o = acc / (sump + 1e-16f) + b2[t];
    __nv_bfloat16 h, l; split_bf16(o, h, l);
    o2h[(size_t)dst * Hd + t] = h;
    o2l[(size_t)dst * Hd + t] = l;
}

// ---------------- sequence bookkeeping ----------------
__global__ void k_init_misc(int* __restrict__ len, const float* __restrict__ bih,
                            const float* __restrict__ bhh, float* __restrict__ bs,
                            float* __restrict__ h)
{
    int i = blockIdx.x * blockDim.x + threadIdx.x;
    if (i < Bsz) len[i] = 0;
    if (i < G4) bs[i] = bih[i] + bhh[i];
    h[i] = 0.f;
}
__global__ void k_count_len(const int* __restrict__ batch, int* __restrict__ len)
{
    int i = blockIdx.x * blockDim.x + threadIdx.x;
    if (i < Nn) atomicAdd(&len[batch[i]], 1);
}
__global__ void k_scan256(const int* __restrict__ len, int* __restrict__ starts)
{
    __shared__ int wsum[8];
    int tid = threadIdx.x;
    int orig = len[tid];
    int v = orig;
    int lane = tid & 31, wid = tid >> 5;
#pragma unroll
    for (int o = 1; o < 32; o <<= 1) {
        int t2 = __shfl_up_sync(0xffffffffu, v, o);
        if (lane >= o) v += t2;
    }
    if (lane == 31) wsum[wid] = v;
    __syncthreads();
    if (tid == 0) {
        int s = 0;
#pragma unroll
        for (int u = 0; u < 8; u++) { int t2 = wsum[u]; wsum[u] = s; s += t2; }
    }
    __syncthreads();
    starts[tid] = (v - orig) + wsum[wid];
}
__global__ void k_nodeidx(const int* __restrict__ batch, const int* __restrict__ starts,
                          int* __restrict__ nodeidx)
{
    int i = blockIdx.x * blockDim.x + threadIdx.x;
    if (i < Nn) {
        int b = batch[i];
        int p = i - starts[b];
        if (p >= 0 && p < Lseq) nodeidx[b * Lseq + p] = i;
    }
}

// ---------------- persistent fused LSTM (4x8 tile, ksplit=4 — R10 config) ----------------
#define WST 68
__global__ void __launch_bounds__(256, 1)
k_lstm(const float* __restrict__ xg, const int* __restrict__ nodeidx,
       const int* __restrict__ len, float* __restrict__ hbuf0,
       float* __restrict__ hbuf1, const float* __restrict__ Whh)
{
    extern __shared__ float sm[];
    float* WshT = sm;
    float* HshT = sm + 256 * WST;
    float* red  = HshT + 256 * 33;
    float* csh  = red + 4 * 64 * 33;

    const int tid  = threadIdx.x;
    const int jb   = blockIdx.x & 15;
    const int mb   = blockIdx.x >> 4;
    const int kg   = tid >> 6;
    const int t64  = tid & 63;
    const int rowq = t64 & 15;
    const int bq   = t64 >> 4;

    unsigned my_gen = atomicAdd(&g_bar_gen, 0u);

    for (int idx = tid; idx < 64 * 256; idx += 256) {
        int r = idx >> 8;
        int k = idx & 255;
        int g = r >> 4, u = r & 15;
        WshT[k * WST + r] = Whh[(size_t)(g * 256 + jb * 16 + u) * 256 + k];
    }
    if (tid < 256) { csh[tid] = 0.f; csh[tid + 256] = 0.f; }

    for (int t = 0; t < Lseq; t++) {
        const float* hc = (t & 1) ? hbuf1 : hbuf0;
#pragma unroll
        for (int l = 0; l < 32; l++) {
            int idx = tid + l * 256;
            int bl = idx >> 8, k = idx & 255;
            HshT[k * 33 + bl] = __ldcg(&hc[(mb * 32 + bl) * 256 + k]);
        }
        __syncthreads();

        float acc[4][8];
#pragma unroll
        for (int i = 0; i < 4; i++)
#pragma unroll
            for (int j = 0; j < 8; j++) acc[i][j] = 0.f;
        const int k0 = kg * 64;
#pragma unroll 4
        for (int k = k0; k < k0 + 64; k++) {
            float4 w = *reinterpret_cast<const float4*>(&WshT[k * WST + rowq * 4]);
            const float* hr = &HshT[k * 33 + bq * 8];
#pragma unroll
            for (int j = 0; j < 8; j++) {
                float hv = hr[j];
                acc[0][j] += w.x * hv;
                acc[1][j] += w.y * hv;
                acc[2][j] += w.z * hv;
                acc[3][j] += w.w * hv;
            }
        }
#pragma unroll
        for (int i = 0; i < 4; i++)
#pragma unroll
            for (int j = 0; j < 8; j++)
                red[kg * (64 * 33) + (rowq * 4 + i) * 33 + bq * 8 + j] = acc[i][j];
        __syncthreads();

        float* hn_buf = (t & 1) ? hbuf0 : hbuf1;
#pragma unroll
        for (int p = tid; p < 512; p += 256) {
            int u = p & 15;
            int bl = p >> 4;
            int bglob = mb * 32 + bl;
            int node = nodeidx[bglob * Lseq + t];
            const float* xp = xg + (size_t)node * G4 + jb * 16 + u;
            float gi = 0.f, gf = 0.f, gg = 0.f, go = 0.f;
#pragma unroll
            for (int q = 0; q < 4; q++) {
                const float* rq = red + q * (64 * 33);
                gi += rq[(0 * 16 + u) * 33 + bl];
                gf += rq[(1 * 16 + u) * 33 + bl];
                gg += rq[(2 * 16 + u) * 33 + bl];
                go += rq[(3 * 16 + u) * 33 + bl];
            }
            gi += xp[0]; gf += xp[256]; gg += xp[512]; go += xp[768];
            float hprev = HshT[(jb * 16 + u) * 33 + bl];
            float cprev = csh[u * 32 + bl];
            float si = 1.f / (1.f + expf(-gi));
            float sf = 1.f / (1.f + expf(-gf));
            float so = 1.f / (1.f + expf(-go));
            float cn = sf * cprev + si * tanhf(gg);
            float hn = so * tanhf(cn);
            bool act = (t < len[bglob]);
            if (act) csh[u * 32 + bl] = cn;
            float hw = act ? hn : hprev;
            __stcg(&hn_buf[bglob * 256 + jb * 16 + u], hw);
        }

        if (t != Lseq - 1) {
            __threadfence();
            __syncthreads();
            if (tid == 0) {
                unsigned old = atomicAdd(&g_bar_arrive, 1u);
                if (old == LSTM_BLOCKS - 1) {
                    atomicExch(&g_bar_arrive, 0u);
                    __threadfence();
                    atomicAdd(&g_bar_gen, 1u);
                } else {
                    while (atomicAdd(&g_bar_gen, 0u) == my_gen) __nanosleep(64);
                }
            }
            __syncthreads();
            my_gen++;
        }
    }
}

// ---------------- host launcher ----------------
extern "C" void kernel_launch(void* const* d_in, const int* in_sizes, int n_in,
                              void* d_out, int out_size)
{
    const int*   x_ids = (const int*)d_in[0];
    const int*   ei    = (const int*)d_in[1];
    const int*   batch = (const int*)d_in[2];
    const float* emb   = (const float*)d_in[3];
    const float* W1    = (const float*)d_in[4];
    const float* attS1 = (const float*)d_in[5];
    const float* attD1 = (const float*)d_in[6];
    const float* b1    = (const float*)d_in[7];
    const float* W2    = (const float*)d_in[8];
    const float* attS2 = (const float*)d_in[9];
    const float* attD2 = (const float*)d_in[10];
    const float* b2    = (const float*)d_in[11];
    const float* Wih   = (const float*)d_in[12];
    const float* Whh   = (const float*)d_in[13];
    const float* bih   = (const float*)d_in[14];
    const float* bhh   = (const float*)d_in[15];
    const float* Wp    = (const float*)d_in[16];
    const float* bp    = (const float*)d_in[17];
    float* out = (float*)d_out;

    void* p;
    cudaGetSymbolAddress(&p, g_h1);      float* h1   = (float*)p;
    cudaGetSymbolAddress(&p, g_h2);      float* h2   = (float*)p;
    cudaGetSymbolAddress(&p, g_xg);      float* xg   = (float*)p;
    cudaGetSymbolAddress(&p, g_as1);     float* as1  = (float*)p;
    cudaGetSymbolAddress(&p, g_ad1);     float* ad1  = (float*)p;
    cudaGetSymbolAddress(&p, g_as2);     float* as2  = (float*)p;
    cudaGetSymbolAddress(&p, g_ad2);     float* ad2  = (float*)p;
    cudaGetSymbolAddress(&p, g_counts);  int* counts = (int*)p;
    cudaGetSymbolAddress(&p, g_rowptr);  int* rowptr = (int*)p;
    cudaGetSymbolAddress(&p, g_cursor);  int* cursor = (int*)p;
    cudaGetSymbolAddress(&p, g_colsrc);  int* colsrc = (int*)p;
    cudaGetSymbolAddress(&p, g_len);     int* len    = (int*)p;
    cudaGetSymbolAddress(&p, g_starts);  int* starts = (int*)p;
    cudaGetSymbolAddress(&p, g_nodeidx); int* nodeidx= (int*)p;
    cudaGetSymbolAddress(&p, g_hbuf1);   float* hb1  = (float*)p;
    cudaGetSymbolAddress(&p, g_h);       float* hS   = (float*)p;
    cudaGetSymbolAddress(&p, g_bsum);    float* bsum = (float*)p;

    __nv_bfloat16 *x0h, *x0l, *x1h, *x1l, *o2h, *o2l;
    __nv_bfloat16 *W1Th, *W1Tl, *W2Th, *W2Tl, *Wihh, *Wihl, *hTh, *hTl, *Wph, *Wpl;
    cudaGetSymbolAddress(&p, g_x0h); x0h = (__nv_bfloat16*)p;
    cudaGetSymbolAddress(&p, g_x0l); x0l = (__nv_bfloat16*)p;
    cudaGetSymbolAddress(&p, g_x1h); x1h = (__nv_bfloat16*)p;
    cudaGetSymbolAddress(&p, g_x1l); x1l = (__nv_bfloat16*)p;
    cudaGetSymbolAddress(&p, g_o2h); o2h = (__nv_bfloat16*)p;
    cudaGetSymbolAddress(&p, g_o2l); o2l = (__nv_bfloat16*)p;
    cudaGetSymbolAddress(&p, g_W1Th); W1Th = (__nv_bfloat16*)p;
    cudaGetSymbolAddress(&p, g_W1Tl); W1Tl = (__nv_bfloat16*)p;
    cudaGetSymbolAddress(&p, g_W2Th); W2Th = (__nv_bfloat16*)p;
    cudaGetSymbolAddress(&p, g_W2Tl); W2Tl = (__nv_bfloat16*)p;
    cudaGetSymbolAddress(&p, g_Wihh); Wihh = (__nv_bfloat16*)p;
    cudaGetSymbolAddress(&p, g_Wihl); Wihl = (__nv_bfloat16*)p;
    cudaGetSymbolAddress(&p, g_hTh);  hTh  = (__nv_bfloat16*)p;
    cudaGetSymbolAddress(&p, g_hTl);  hTl  = (__nv_bfloat16*)p;
    cudaGetSymbolAddress(&p, g_Wph);  Wph  = (__nv_bfloat16*)p;
    cudaGetSymbolAddress(&p, g_Wpl);  Wpl  = (__nv_bfloat16*)p;

    static const int LSTM_SMEM = (256 * WST + 256 * 33 + 4 * 64 * 33 + 512) * 4;
    cudaFuncSetAttribute(k_lstm, cudaFuncAttributeMaxDynamicSharedMemorySize, LSTM_SMEM);
    cudaFuncSetAttribute(k_gemm_bf3, cudaFuncAttributeMaxDynamicSharedMemorySize, GEMM_SMEM);

    // second stream + fork/join events (fresh per call; kernel_launch runs only
    // a handful of times — correctness + capture — so the leak is bounded)
    cudaStream_t s2;
    cudaStreamCreateWithFlags(&s2, cudaStreamNonBlocking);
    cudaEvent_t evFork, evJoin;
    cudaEventCreateWithFlags(&evFork, cudaEventDisableTiming);
    cudaEventCreateWithFlags(&evJoin, cudaEventDisableTiming);

    // ---- main stream: GEMM1 dependency chain ----
    k_gather_x0<<<Nn, Hd>>>(x_ids, emb, x0h, x0l);
    k_splitT<<<dim3(F1 / 32, Hd / 32), dim3(32, 8)>>>(W1, W1Th, W1Tl, Hd, F1);

    // ---- fork: all GEMM1-independent prep on s2 ----
    cudaEventRecord(evFork, 0);
    cudaStreamWaitEvent(s2, evFork, 0);
    k_splitT<<<dim3(Hd / 32, F1 / 32), dim3(32, 8), 0, s2>>>(W2, W2Th, W2Tl, F1, Hd);
    k_split<<<(G4 * Hd + 255) / 256, 256, 0, s2>>>(Wih, Wihh, Wihl, G4 * Hd);
    k_split<<<(NNODE_ * Hd + 255) / 256, 256, 0, s2>>>(Wp, Wph, Wpl, NNODE_ * Hd);
    k_init_counts<<<Nn / 256, 256, 0, s2>>>(counts);
    k_count_edges<<<Ee / 256, 256, 0, s2>>>(ei, counts);
    k_scan16k<<<1, 1024, 0, s2>>>(counts, rowptr, cursor);
    k_scatter_edges<<<Ee / 256, 256, 0, s2>>>(ei, cursor, colsrc);
    k_scatter_loops<<<Nn / 256, 256, 0, s2>>>(cursor, colsrc);
    k_init_misc<<<(Bsz * Hd) / 256, 256, 0, s2>>>(len, bih, bhh, bsum, hS);
    k_count_len<<<Nn / 256, 256, 0, s2>>>(batch, len);
    k_scan256<<<1, Bsz, 0, s2>>>(len, starts);
    k_nodeidx<<<Nn / 256, 256, 0, s2>>>(batch, starts, nodeidx);
    cudaEventRecord(evJoin, s2);

    // ---- main stream continues in parallel ----
    k_gemm_bf3<<<dim3(F1 / GBN, Nn / GBM), 256, GEMM_SMEM>>>(
        x0h, x0l, W1Th, W1Tl, h1, Nn, F1, Hd, nullptr);
    k_alpha1<<<Nn, 256>>>(h1, attS1, attD1, as1, ad1);

    // ---- join: gat1 needs the CSR from s2 ----
    cudaStreamWaitEvent(0, evJoin, 0);

    k_gat1_agg<<<Nn, 256>>>(h1, as1, ad1, rowptr, colsrc, b1, x1h, x1l);

    k_gemm_bf3<<<dim3(Hd / GBN, Nn / GBM), 256, GEMM_SMEM>>>(
        x1h, x1l, W2Th, W2Tl, h2, Nn, Hd, F1, nullptr);

    k_alpha2<<<Nn, 256>>>(h2, attS2, attD2, as2, ad2);
    k_gat2_agg<<<Nn, 256>>>(h2, as2, ad2, rowptr, colsrc, b2, o2h, o2l);

    k_gemm_bf3<<<dim3(G4 / GBN, Nn / GBM), 256, GEMM_SMEM>>>(
        o2h, o2l, Wihh, Wihl, xg, Nn, G4, Hd, bsum);

    k_lstm<<<LSTM_BLOCKS, 256, LSTM_SMEM>>>(xg, nodeidx, len, hS, hb1, Whh);

    k_split<<<(Bsz * Hd + 255) / 256, 256>>>(hS, hTh, hTl, Bsz * Hd);
    k_gemm_bf3<<<dim3((NNODE_ + GBN - 1) / GBN, Bsz / GBM), 256, GEMM_SMEM>>>(
        hTh, hTl, Wph, Wpl, out, Bsz, NNODE_, Hd, bp);
}

// round 13
// speedup vs baseline: 1.0494x; 1.0146x over previous
#include <cuda_runtime.h>
#include <cuda_bf16.h>
#include <stdint.h>
#include <math.h>

typedef unsigned int u32;

// ---------------- problem constants ----------------
#define Nn      16384
#define Ee      131072
#define ETOT    (Ee + Nn)
#define Bsz     256
#define Lseq    64
#define Hd      256
#define NHEADS  8
#define F1      2048
#define G4      1024
#define NNODE_  37000

#define LSTM_BLOCKS 128

// ---------------- device scratch ----------------
__device__ float g_h1  [(size_t)Nn * F1];
__device__ float g_h2  [(size_t)Nn * Hd];
__device__ float g_xg  [(size_t)Nn * G4];
__device__ float g_as1 [Nn * NHEADS];
__device__ float g_ad1 [Nn * NHEADS];
__device__ float g_as2 [Nn];
__device__ float g_ad2 [Nn];
__device__ int   g_counts[Nn];
__device__ int   g_rowptr[Nn + 1];
__device__ int   g_cursor[Nn];
__device__ int   g_colsrc[ETOT];
__device__ int   g_len   [Bsz];
__device__ int   g_starts[Bsz];
__device__ int   g_nodeidx[Bsz * Lseq];
__device__ float g_hbuf1[Bsz * Hd];
__device__ float g_h    [Bsz * Hd];
__device__ float g_bsum [G4];
// per-mb-group barrier state: 8 groups, each on its own 128B line
__device__ unsigned g_grp_arrive[8 * 32];
__device__ unsigned g_grp_gen   [8 * 32];

// bf16 hi/lo split operands for tensor-core GEMMs
__device__ __nv_bfloat16 g_x0h[(size_t)Nn * Hd],  g_x0l[(size_t)Nn * Hd];
__device__ __nv_bfloat16 g_x1h[(size_t)Nn * F1],  g_x1l[(size_t)Nn * F1];
__device__ __nv_bfloat16 g_o2h[(size_t)Nn * Hd],  g_o2l[(size_t)Nn * Hd];
__device__ __nv_bfloat16 g_W1Th[(size_t)F1 * Hd], g_W1Tl[(size_t)F1 * Hd];
__device__ __nv_bfloat16 g_W2Th[(size_t)Hd * F1], g_W2Tl[(size_t)Hd * F1];
__device__ __nv_bfloat16 g_Wihh[(size_t)G4 * Hd], g_Wihl[(size_t)G4 * Hd];
__device__ __nv_bfloat16 g_hTh[Bsz * Hd],         g_hTl[Bsz * Hd];
__device__ __nv_bfloat16 g_Wph[(size_t)NNODE_ * Hd], g_Wpl[(size_t)NNODE_ * Hd];

// ---------------- small helpers ----------------
__device__ __forceinline__ void split_bf16(float v, __nv_bfloat16& h, __nv_bfloat16& l)
{
    h = __float2bfloat16(v);
    l = __float2bfloat16(v - __bfloat162float(h));
}
__device__ __forceinline__ u32 smem_u32(const void* p)
{
    return (u32)__cvta_generic_to_shared(p);
}
__device__ __forceinline__ void cp16(u32 dst, const void* src, int srcsize)
{
    asm volatile("cp.async.cg.shared.global [%0], [%1], 16, %2;"
                 :: "r"(dst), "l"(src), "r"(srcsize) : "memory");
}
__device__ __forceinline__ void cp_commit()
{
    asm volatile("cp.async.commit_group;" ::: "memory");
}
template<int NG>
__device__ __forceinline__ void cp_wait()
{
    asm volatile("cp.async.wait_group %0;" :: "n"(NG) : "memory");
}
__device__ __forceinline__ void ldsm_x4(u32 a, u32& r0, u32& r1, u32& r2, u32& r3)
{
    asm volatile("ldmatrix.sync.aligned.m8n8.x4.shared.b16 {%0,%1,%2,%3},[%4];"
                 : "=r"(r0), "=r"(r1), "=r"(r2), "=r"(r3) : "r"(a));
}
__device__ __forceinline__ void mma16816(float* c, u32 a0, u32 a1, u32 a2, u32 a3,
                                         u32 b0, u32 b1)
{
    asm volatile("mma.sync.aligned.m16n8k16.row.col.f32.bf16.bf16.f32 "
                 "{%0,%1,%2,%3},{%4,%5,%6,%7},{%8,%9},{%0,%1,%2,%3};"
                 : "+f"(c[0]), "+f"(c[1]), "+f"(c[2]), "+f"(c[3])
                 : "r"(a0), "r"(a1), "r"(a2), "r"(a3), "r"(b0), "r"(b1));
}

// ---------------- bf16x3 tensor-core GEMM (256 threads, 2 CTAs/SM) ----------------
#define GBM 128
#define GBN 128
#define GBK 32
#define BROW 40
#define ABUF (GBM * BROW)
#define GEMM_SMEM (8 * ABUF * 2)

__global__ void __launch_bounds__(256, 2)
k_gemm_bf3(const __nv_bfloat16* __restrict__ Ah, const __nv_bfloat16* __restrict__ Al,
           const __nv_bfloat16* __restrict__ Bh, const __nv_bfloat16* __restrict__ Bl,
           float* __restrict__ C, int M, int N, int K, const float* __restrict__ bias)
{
    extern __shared__ __nv_bfloat16 smg[];
    __nv_bfloat16* As = smg;
    __nv_bfloat16* Bs = smg + 4 * ABUF;
    const u32 sA = smem_u32(As);
    const u32 sB = smem_u32(Bs);

    const int tid  = threadIdx.x;
    const int bm   = blockIdx.y * GBM;
    const int bn   = blockIdx.x * GBN;
    const int warp = tid >> 5, lane = tid & 31;
    const int wm   = (warp >> 2) * 64;
    const int wn   = (warp & 3) * 32;

    float acc[4][4][4];
#pragma unroll
    for (int i = 0; i < 4; i++)
#pragma unroll
        for (int j = 0; j < 4; j++)
#pragma unroll
            for (int u = 0; u < 4; u++) acc[i][j][u] = 0.f;

    const int nstage = K / GBK;

    auto loadstage = [&](int kt, int st) {
        const int k0 = kt * GBK;
#pragma unroll
        for (int l = 0; l < 2; l++) {
            int i = tid + l * 256;
            int r = i >> 2, s = (i & 3) * 8;
            u32 doff = (u32)((r * BROW + s) * 2);
            size_t ga = (size_t)(bm + r) * K + k0 + s;
            cp16(sA + (u32)(st * 2 + 0) * (ABUF * 2) + doff, Ah + ga, 16);
            cp16(sA + (u32)(st * 2 + 1) * (ABUF * 2) + doff, Al + ga, 16);
            int nrow = bn + r;
            int ok = (nrow < N) ? 16 : 0;
            int nc = (nrow < N) ? nrow : (N - 1);
            size_t gb = (size_t)nc * K + k0 + s;
            cp16(sB + (u32)(st * 2 + 0) * (ABUF * 2) + doff, Bh + gb, ok);
            cp16(sB + (u32)(st * 2 + 1) * (ABUF * 2) + doff, Bl + gb, ok);
        }
        cp_commit();
    };

    loadstage(0, 0);
    int st = 0;
    for (int kt = 0; kt < nstage; kt++) {
        if (kt + 1 < nstage) { loadstage(kt + 1, st ^ 1); cp_wait<1>(); }
        else                 { cp_wait<0>(); }
        __syncthreads();

#pragma unroll
        for (int kk = 0; kk < 2; kk++) {
            u32 bfh[4][2], bfl[4][2];
#pragma unroll
            for (int half = 0; half < 2; half++) {
                int g = lane >> 3;
                u32 off = (u32)(((wn + half * 16 + (g & 1) * 8 + (lane & 7)) * BROW
                          + kk * 16 + (g >> 1) * 8) * 2);
                u32 r0, r1, r2, r3;
                ldsm_x4(sB + (u32)(st * 2 + 0) * (ABUF * 2) + off, r0, r1, r2, r3);
                bfh[half * 2 + 0][0] = r0; bfh[half * 2 + 1][0] = r1;
                bfh[half * 2 + 0][1] = r2; bfh[half * 2 + 1][1] = r3;
                ldsm_x4(sB + (u32)(st * 2 + 1) * (ABUF * 2) + off, r0, r1, r2, r3);
                bfl[half * 2 + 0][0] = r0; bfl[half * 2 + 1][0] = r1;
                bfl[half * 2 + 0][1] = r2; bfl[half * 2 + 1][1] = r3;
            }
#pragma unroll
            for (int mh = 0; mh < 2; mh++) {
                u32 afh[2][4], afl[2][4];
#pragma unroll
                for (int m2 = 0; m2 < 2; m2++) {
                    int mt = mh * 2 + m2;
                    u32 off = (u32)(((wm + mt * 16 + (lane & 15)) * BROW
                              + kk * 16 + (lane >> 4) * 8) * 2);
                    ldsm_x4(sA + (u32)(st * 2 + 0) * (ABUF * 2) + off,
                            afh[m2][0], afh[m2][1], afh[m2][2], afh[m2][3]);
                    ldsm_x4(sA + (u32)(st * 2 + 1) * (ABUF * 2) + off,
                            afl[m2][0], afl[m2][1], afl[m2][2], afl[m2][3]);
                }
#pragma unroll
                for (int m2 = 0; m2 < 2; m2++)
#pragma unroll
                    for (int nt = 0; nt < 4; nt++) {
                        float* a = acc[mh * 2 + m2][nt];
                        mma16816(a, afh[m2][0], afh[m2][1], afh[m2][2], afh[m2][3],
                                 bfh[nt][0], bfh[nt][1]);
                        mma16816(a, afh[m2][0], afh[m2][1], afh[m2][2], afh[m2][3],
                                 bfl[nt][0], bfl[nt][1]);
                        mma16816(a, afl[m2][0], afl[m2][1], afl[m2][2], afl[m2][3],
                                 bfh[nt][0], bfh[nt][1]);
                    }
            }
        }
        __syncthreads();
        st ^= 1;
    }

#pragma unroll
    for (int mt = 0; mt < 4; mt++) {
        int row0 = bm + wm + mt * 16 + (lane >> 2);
#pragma unroll
        for (int nt = 0; nt < 4; nt++) {
            int col = bn + wn + nt * 8 + (lane & 3) * 2;
            if (col < N) {
                float b0 = bias ? bias[col] : 0.f;
                float b1 = bias ? bias[col + 1] : 0.f;
                float2 v0 = make_float2(acc[mt][nt][0] + b0, acc[mt][nt][1] + b1);
                float2 v1 = make_float2(acc[mt][nt][2] + b0, acc[mt][nt][3] + b1);
                *reinterpret_cast<float2*>(&C[(size_t)row0 * N + col]) = v0;
                *reinterpret_cast<float2*>(&C[(size_t)(row0 + 8) * N + col]) = v1;
            }
        }
    }
}

// ---------------- split conversions ----------------
__global__ void k_split(const float* __restrict__ x, __nv_bfloat16* __restrict__ hi,
                        __nv_bfloat16* __restrict__ lo, int n)
{
    int i = blockIdx.x * blockDim.x + threadIdx.x;
    if (i < n) { __nv_bfloat16 h, l; split_bf16(x[i], h, l); hi[i] = h; lo[i] = l; }
}
__global__ void k_splitT(const float* __restrict__ W, __nv_bfloat16* __restrict__ hiT,
                         __nv_bfloat16* __restrict__ loT, int K, int N)
{
    __shared__ float tile[32][33];
    int k0 = blockIdx.y * 32, n0 = blockIdx.x * 32;
    int tx = threadIdx.x, ty = threadIdx.y;
    for (int i = ty; i < 32; i += 8)
        tile[i][tx] = W[(size_t)(k0 + i) * N + n0 + tx];
    __syncthreads();
    for (int i = ty; i < 32; i += 8) {
        float v = tile[tx][i];
        __nv_bfloat16 h, l; split_bf16(v, h, l);
        size_t o = (size_t)(n0 + i) * K + k0 + tx;
        hiT[o] = h; loT[o] = l;
    }
}

// ---------------- embedding gather + split ----------------
__global__ void k_gather_x0(const int* __restrict__ ids, const float* __restrict__ emb,
                            __nv_bfloat16* __restrict__ x0h, __nv_bfloat16* __restrict__ x0l)
{
    int i = blockIdx.x, t = threadIdx.x;
    int id = ids[i];
    float v = (id == 0) ? 0.f : emb[(size_t)id * Hd + t];
    __nv_bfloat16 h, l; split_bf16(v, h, l);
    x0h[(size_t)i * Hd + t] = h;
    x0l[(size_t)i * Hd + t] = l;
}

// ---------------- attention logits ----------------
__global__ void k_alpha1(const float* __restrict__ h1, const float* __restrict__ attS,
                         const float* __restrict__ attD,
                         float* __restrict__ outS, float* __restrict__ outD)
{
    int i = blockIdx.x;
    int w = threadIdx.x >> 5, lane = threadIdx.x & 31;
    const float* hp = h1 + (size_t)i * F1 + w * Hd;
    const float* ap = attS + w * Hd;
    const float* dp = attD + w * Hd;
    float ss = 0.f, sd = 0.f;
#pragma unroll
    for (int u = 0; u < 8; u++) {
        float v = hp[lane + 32 * u];
        ss += v * ap[lane + 32 * u];
        sd += v * dp[lane + 32 * u];
    }
#pragma unroll
    for (int o = 16; o; o >>= 1) {
        ss += __shfl_xor_sync(0xffffffffu, ss, o);
        sd += __shfl_xor_sync(0xffffffffu, sd, o);
    }
    if (lane == 0) { outS[i * NHEADS + w] = ss; outD[i * NHEADS + w] = sd; }
}

__global__ void k_alpha2(const float* __restrict__ h2, const float* __restrict__ attS,
                         const float* __restrict__ attD,
                         float* __restrict__ outS, float* __restrict__ outD)
{
    __shared__ float shS[8], shD[8];
    int i = blockIdx.x, t = threadIdx.x;
    float v = h2[(size_t)i * Hd + t];
    float ss = v * attS[t], sd = v * attD[t];
    int lane = t & 31, w = t >> 5;
#pragma unroll
    for (int o = 16; o; o >>= 1) {
        ss += __shfl_xor_sync(0xffffffffu, ss, o);
        sd += __shfl_xor_sync(0xffffffffu, sd, o);
    }
    if (lane == 0) { shS[w] = ss; shD[w] = sd; }
    __syncthreads();
    if (t == 0) {
        float a = 0.f, b = 0.f;
#pragma unroll
        for (int u = 0; u < 8; u++) { a += shS[u]; b += shD[u]; }
        outS[i] = a; outD[i] = b;
    }
}

// ---------------- CSR build ----------------
__global__ void k_init_counts(int* __restrict__ counts)
{
    int i = blockIdx.x * blockDim.x + threadIdx.x;
    if (i < Nn) counts[i] = 1;
}
__global__ void k_count_edges(const int* __restrict__ ei, int* __restrict__ counts)
{
    int e = blockIdx.x * blockDim.x + threadIdx.x;
    if (e < Ee) atomicAdd(&counts[ei[Ee + e]], 1);
}
__global__ void k_scan16k(const int* __restrict__ counts, int* __restrict__ rowptr,
                          int* __restrict__ cursor)
{
    __shared__ int wsum[32];
    const int tid = threadIdx.x;
    const int per = Nn / 1024;
    const int base = tid * per;
    int c[16];
    int tot = 0;
#pragma unroll
    for (int u = 0; u < per; u++) { c[u] = counts[base + u]; tot += c[u]; }
    int lane = tid & 31, wid = tid >> 5;
    int v = tot;
#pragma unroll
    for (int o = 1; o < 32; o <<= 1) {
        int t2 = __shfl_up_sync(0xffffffffu, v, o);
        if (lane >= o) v += t2;
    }
    if (lane == 31) wsum[wid] = v;
    __syncthreads();
    if (wid == 0) {
        int w = wsum[lane];
#pragma unroll
        for (int o = 1; o < 32; o <<= 1) {
            int t2 = __shfl_up_sync(0xffffffffu, w, o);
            if (lane >= o) w += t2;
        }
        wsum[lane] = w;
    }
    __syncthreads();
    int run = (v - tot) + (wid > 0 ? wsum[wid - 1] : 0);
#pragma unroll
    for (int u = 0; u < per; u++) {
        rowptr[base + u] = run;
        cursor[base + u] = run;
        run += c[u];
    }
    if (tid == 1023) rowptr[Nn] = run;
}
__global__ void k_scatter_edges(const int* __restrict__ ei,
                                int* __restrict__ cursor, int* __restrict__ colsrc)
{
    int e = blockIdx.x * blockDim.x + threadIdx.x;
    if (e < Ee) {
        int d = ei[Ee + e];
        int p = atomicAdd(&cursor[d], 1);
        colsrc[p] = ei[e];
    }
}
__global__ void k_scatter_loops(int* __restrict__ cursor, int* __restrict__ colsrc)
{
    int i = blockIdx.x * blockDim.x + threadIdx.x;
    if (i < Nn) {
        int p = atomicAdd(&cursor[i], 1);
        colsrc[p] = i;
    }
}

// ---------------- GAT aggregation (two-pass softmax, fused bf16 split) ----------------
__global__ void k_gat1_agg(const float* __restrict__ h1,
                           const float* __restrict__ aS, const float* __restrict__ aD,
                           const int* __restrict__ rowptr, const int* __restrict__ colsrc,
                           const float* __restrict__ b1,
                           __nv_bfloat16* __restrict__ x1h, __nv_bfloat16* __restrict__ x1l)
{
    int dst = blockIdx.x;
    int w = threadIdx.x >> 5, lane = threadIdx.x & 31;
    int beg = rowptr[dst], end = rowptr[dst + 1];
    float adv = aD[dst * NHEADS + w];

    float m = -3.4e38f;
    for (int e = beg; e < end; e++) {
        float v = aS[colsrc[e] * NHEADS + w] + adv;
        v = v > 0.f ? v : 0.2f * v;
        m = fmaxf(m, v);
    }
    float acc[8] = {0.f, 0.f, 0.f, 0.f, 0.f, 0.f, 0.f, 0.f};
    float sump = 0.f;
    for (int e = beg; e < end; e++) {
        int s = colsrc[e];
        float v = aS[s * NHEADS + w] + adv;
        v = v > 0.f ? v : 0.2f * v;
        float p = expf(v - m);
        sump += p;
        const float* hp = h1 + (size_t)s * F1 + w * Hd + lane;
#pragma unroll
        for (int u = 0; u < 8; u++) acc[u] += p * hp[u * 32];
    }
    float inv = 1.f / (sump + 1e-16f);
    size_t base = (size_t)dst * F1 + w * Hd + lane;
    const float* bp = b1 + w * Hd + lane;
#pragma unroll
    for (int u = 0; u < 8; u++) {
        float o = acc[u] * inv + bp[u * 32];
        o = o > 0.f ? o : expm1f(o);           // ELU
        __nv_bfloat16 h, l; split_bf16(o, h, l);
        x1h[base + u * 32] = h;
        x1l[base + u * 32] = l;
    }
}

__global__ void k_gat2_agg(const float* __restrict__ h2,
                           const float* __restrict__ aS, const float* __restrict__ aD,
                           const int* __restrict__ rowptr, const int* __restrict__ colsrc,
                           const float* __restrict__ b2,
                           __nv_bfloat16* __restrict__ o2h, __nv_bfloat16* __restrict__ o2l)
{
    int dst = blockIdx.x, t = threadIdx.x;
    int beg = rowptr[dst], end = rowptr[dst + 1];
    float adv = aD[dst];
    float m = -3.4e38f;
    for (int e = beg; e < end; e++) {
        float v = aS[colsrc[e]] + adv;
        v = v > 0.f ? v : 0.2f * v;
        m = fmaxf(m, v);
    }
    float acc = 0.f, sump = 0.f;
    for (int e = beg; e < end; e++) {
        int s = colsrc[e];
        float v = aS[s] + adv;
        v = v > 0.f ? v : 0.2f * v;
        float p = expf(v - m);
        sump += p;
        acc += p * h2[(size_t)s * Hd + t];
    }
    float o = acc / (sump + 1e-16f) + b2[t];
    __nv_bfloat16 h, l; split_bf16(o, h, l);
    o2h[(size_t)dst * Hd + t] = h;
    o2l[(size_t)dst * Hd + t] = l;
}

// ---------------- sequence bookkeeping ----------------
__global__ void k_init_misc(int* __restrict__ len, const float* __restrict__ bih,
                            const float* __restrict__ bhh, float* __restrict__ bs,
                            float* __restrict__ h)
{
    int i = blockIdx.x * blockDim.x + threadIdx.x;
    if (i < Bsz) len[i] = 0;
    if (i < G4) bs[i] = bih[i] + bhh[i];
    h[i] = 0.f;
}
__global__ void k_count_len(const int* __restrict__ batch, int* __restrict__ len)
{
    int i = blockIdx.x * blockDim.x + threadIdx.x;
    if (i < Nn) atomicAdd(&len[batch[i]], 1);
}
__global__ void k_scan256(const int* __restrict__ len, int* __restrict__ starts)
{
    __shared__ int wsum[8];
    int tid = threadIdx.x;
    int orig = len[tid];
    int v = orig;
    int lane = tid & 31, wid = tid >> 5;
#pragma unroll
    for (int o = 1; o < 32; o <<= 1) {
        int t2 = __shfl_up_sync(0xffffffffu, v, o);
        if (lane >= o) v += t2;
    }
    if (lane == 31) wsum[wid] = v;
    __syncthreads();
    if (tid == 0) {
        int s = 0;
#pragma unroll
        for (int u = 0; u < 8; u++) { int t2 = wsum[u]; wsum[u] = s; s += t2; }
    }
    __syncthreads();
    starts[tid] = (v - orig) + wsum[wid];
}
__global__ void k_nodeidx(const int* __restrict__ batch, const int* __restrict__ starts,
                          int* __restrict__ nodeidx)
{
    int i = blockIdx.x * blockDim.x + threadIdx.x;
    if (i < Nn) {
        int b = batch[i];
        int p = i - starts[b];
        if (p >= 0 && p < Lseq) nodeidx[b * Lseq + p] = i;
    }
}

// ---------------- persistent fused LSTM ----------------
// 16-block barriers per mb-group (blocks sharing mb only touch their own
// 32-batch rows of the h double-buffer), spin-poll without nanosleep.
#define WST 68
__global__ void __launch_bounds__(256, 1)
k_lstm(const float* __restrict__ xg, const int* __restrict__ nodeidx,
       const int* __restrict__ len, float* __restrict__ hbuf0,
       float* __restrict__ hbuf1, const float* __restrict__ Whh)
{
    extern __shared__ float sm[];
    float* WshT = sm;
    float* HshT = sm + 256 * WST;
    float* red  = HshT + 256 * 33;
    float* csh  = red + 4 * 64 * 33;

    const int tid  = threadIdx.x;
    const int jb   = blockIdx.x & 15;
    const int mb   = blockIdx.x >> 4;
    const int kg   = tid >> 6;
    const int t64  = tid & 63;
    const int rowq = t64 & 15;
    const int bq   = t64 >> 4;

    unsigned* grp_arr = &g_grp_arrive[mb * 32];
    unsigned* grp_gen = &g_grp_gen[mb * 32];
    unsigned my_gen = atomicAdd(grp_gen, 0u);

    for (int idx = tid; idx < 64 * 256; idx += 256) {
        int r = idx >> 8;
        int k = idx & 255;
        int g = r >> 4, u = r & 15;
        WshT[k * WST + r] = Whh[(size_t)(g * 256 + jb * 16 + u) * 256 + k];
    }
    if (tid < 256) { csh[tid] = 0.f; csh[tid + 256] = 0.f; }

    for (int t = 0; t < Lseq; t++) {
        const float* hc = (t & 1) ? hbuf1 : hbuf0;
#pragma unroll
        for (int l = 0; l < 32; l++) {
            int idx = tid + l * 256;
            int bl = idx >> 8, k = idx & 255;
            HshT[k * 33 + bl] = __ldcg(&hc[(mb * 32 + bl) * 256 + k]);
        }
        __syncthreads();

        float acc[4][8];
#pragma unroll
        for (int i = 0; i < 4; i++)
#pragma unroll
            for (int j = 0; j < 8; j++) acc[i][j] = 0.f;
        const int k0 = kg * 64;
#pragma unroll 4
        for (int k = k0; k < k0 + 64; k++) {
            float4 w = *reinterpret_cast<const float4*>(&WshT[k * WST + rowq * 4]);
            const float* hr = &HshT[k * 33 + bq * 8];
#pragma unroll
            for (int j = 0; j < 8; j++) {
                float hv = hr[j];
                acc[0][j] += w.x * hv;
                acc[1][j] += w.y * hv;
                acc[2][j] += w.z * hv;
                acc[3][j] += w.w * hv;
            }
        }
#pragma unroll
        for (int i = 0; i < 4; i++)
#pragma unroll
            for (int j = 0; j < 8; j++)
                red[kg * (64 * 33) + (rowq * 4 + i) * 33 + bq * 8 + j] = acc[i][j];
        __syncthreads();

        float* hn_buf = (t & 1) ? hbuf0 : hbuf1;
#pragma unroll
        for (int p = tid; p < 512; p += 256) {
            int u = p & 15;
            int bl = p >> 4;
            int bglob = mb * 32 + bl;
            int node = nodeidx[bglob * Lseq + t];
            const float* xp = xg + (size_t)node * G4 + jb * 16 + u;
            float gi = 0.f, gf = 0.f, gg = 0.f, go = 0.f;
#pragma unroll
            for (int q = 0; q < 4; q++) {
                const float* rq = red + q * (64 * 33);
                gi += rq[(0 * 16 + u) * 33 + bl];
                gf += rq[(1 * 16 + u) * 33 + bl];
                gg += rq[(2 * 16 + u) * 33 + bl];
                go += rq[(3 * 16 + u) * 33 + bl];
            }
            gi += xp[0]; gf += xp[256]; gg += xp[512]; go += xp[768];
            float hprev = HshT[(jb * 16 + u) * 33 + bl];
            float cprev = csh[u * 32 + bl];
            float si = 1.f / (1.f + expf(-gi));
            float sf = 1.f / (1.f + expf(-gf));
            float so = 1.f / (1.f + expf(-go));
            float cn = sf * cprev + si * tanhf(gg);
            float hn = so * tanhf(cn);
            bool act = (t < len[bglob]);
            if (act) csh[u * 32 + bl] = cn;
            float hw = act ? hn : hprev;
            __stcg(&hn_buf[bglob * 256 + jb * 16 + u], hw);
        }

        if (t != Lseq - 1) {
            __threadfence();
            __syncthreads();
            if (tid == 0) {
                unsigned old = atomicAdd(grp_arr, 1u);
                if (old == 15u) {
                    atomicExch(grp_arr, 0u);
                    __threadfence();
                    atomicAdd(grp_gen, 1u);
                } else {
                    while (atomicAdd(grp_gen, 0u) == my_gen) { }
                }
            }
            __syncthreads();
            my_gen++;
        }
    }
}

// ---------------- host launcher ----------------
extern "C" void kernel_launch(void* const* d_in, const int* in_sizes, int n_in,
                              void* d_out, int out_size)
{
    const int*   x_ids = (const int*)d_in[0];
    const int*   ei    = (const int*)d_in[1];
    const int*   batch = (const int*)d_in[2];
    const float* emb   = (const float*)d_in[3];
    const float* W1    = (const float*)d_in[4];
    const float* attS1 = (const float*)d_in[5];
    const float* attD1 = (const float*)d_in[6];
    const float* b1    = (const float*)d_in[7];
    const float* W2    = (const float*)d_in[8];
    const float* attS2 = (const float*)d_in[9];
    const float* attD2 = (const float*)d_in[10];
    const float* b2    = (const float*)d_in[11];
    const float* Wih   = (const float*)d_in[12];
    const float* Whh   = (const float*)d_in[13];
    const float* bih   = (const float*)d_in[14];
    const float* bhh   = (const float*)d_in[15];
    const float* Wp    = (const float*)d_in[16];
    const float* bp    = (const float*)d_in[17];
    float* out = (float*)d_out;

    void* p;
    cudaGetSymbolAddress(&p, g_h1);      float* h1   = (float*)p;
    cudaGetSymbolAddress(&p, g_h2);      float* h2   = (float*)p;
    cudaGetSymbolAddress(&p, g_xg);      float* xg   = (float*)p;
    cudaGetSymbolAddress(&p, g_as1);     float* as1  = (float*)p;
    cudaGetSymbolAddress(&p, g_ad1);     float* ad1  = (float*)p;
    cudaGetSymbolAddress(&p, g_as2);     float* as2  = (float*)p;
    cudaGetSymbolAddress(&p, g_ad2);     float* ad2  = (float*)p;
    cudaGetSymbolAddress(&p, g_counts);  int* counts = (int*)p;
    cudaGetSymbolAddress(&p, g_rowptr);  int* rowptr = (int*)p;
    cudaGetSymbolAddress(&p, g_cursor);  int* cursor = (int*)p;
    cudaGetSymbolAddress(&p, g_colsrc);  int* colsrc = (int*)p;
    cudaGetSymbolAddress(&p, g_len);     int* len    = (int*)p;
    cudaGetSymbolAddress(&p, g_starts);  int* starts = (int*)p;
    cudaGetSymbolAddress(&p, g_nodeidx); int* nodeidx= (int*)p;
    cudaGetSymbolAddress(&p, g_hbuf1);   float* hb1  = (float*)p;
    cudaGetSymbolAddress(&p, g_h);       float* hS   = (float*)p;
    cudaGetSymbolAddress(&p, g_bsum);    float* bsum = (float*)p;

    __nv_bfloat16 *x0h, *x0l, *x1h, *x1l, *o2h, *o2l;
    __nv_bfloat16 *W1Th, *W1Tl, *W2Th, *W2Tl, *Wihh, *Wihl, *hTh, *hTl, *Wph, *Wpl;
    cudaGetSymbolAddress(&p, g_x0h); x0h = (__nv_bfloat16*)p;
    cudaGetSymbolAddress(&p, g_x0l); x0l = (__nv_bfloat16*)p;
    cudaGetSymbolAddress(&p, g_x1h); x1h = (__nv_bfloat16*)p;
    cudaGetSymbolAddress(&p, g_x1l); x1l = (__nv_bfloat16*)p;
    cudaGetSymbolAddress(&p, g_o2h); o2h = (__nv_bfloat16*)p;
    cudaGetSymbolAddress(&p, g_o2l); o2l = (__nv_bfloat16*)p;
    cudaGetSymbolAddress(&p, g_W1Th); W1Th = (__nv_bfloat16*)p;
    cudaGetSymbolAddress(&p, g_W1Tl); W1Tl = (__nv_bfloat16*)p;
    cudaGetSymbolAddress(&p, g_W2Th); W2Th = (__nv_bfloat16*)p;
    cudaGetSymbolAddress(&p, g_W2Tl); W2Tl = (__nv_bfloat16*)p;
    cudaGetSymbolAddress(&p, g_Wihh); Wihh = (__nv_bfloat16*)p;
    cudaGetSymbolAddress(&p, g_Wihl); Wihl = (__nv_bfloat16*)p;
    cudaGetSymbolAddress(&p, g_hTh);  hTh  = (__nv_bfloat16*)p;
    cudaGetSymbolAddress(&p, g_hTl);  hTl  = (__nv_bfloat16*)p;
    cudaGetSymbolAddress(&p, g_Wph);  Wph  = (__nv_bfloat16*)p;
    cudaGetSymbolAddress(&p, g_Wpl);  Wpl  = (__nv_bfloat16*)p;

    static const int LSTM_SMEM = (256 * WST + 256 * 33 + 4 * 64 * 33 + 512) * 4;
    cudaFuncSetAttribute(k_lstm, cudaFuncAttributeMaxDynamicSharedMemorySize, LSTM_SMEM);
    cudaFuncSetAttribute(k_gemm_bf3, cudaFuncAttributeMaxDynamicSharedMemorySize, GEMM_SMEM);

    cudaStream_t s2;
    cudaStreamCreateWithFlags(&s2, cudaStreamNonBlocking);
    cudaEvent_t evFork, evJoin;
    cudaEventCreateWithFlags(&evFork, cudaEventDisableTiming);
    cudaEventCreateWithFlags(&evJoin, cudaEventDisableTiming);

    // ---- main stream: GEMM1 dependency chain ----
    k_gather_x0<<<Nn, Hd>>>(x_ids, emb, x0h, x0l);
    k_splitT<<<dim3(F1 / 32, Hd / 32), dim3(32, 8)>>>(W1, W1Th, W1Tl, Hd, F1);

    // ---- fork: all GEMM1-independent prep on s2 ----
    cudaEventRecord(evFork, 0);
    cudaStreamWaitEvent(s2, evFork, 0);
    k_splitT<<<dim3(Hd / 32, F1 / 32), dim3(32, 8), 0, s2>>>(W2, W2Th, W2Tl, F1, Hd);
    k_split<<<(G4 * Hd + 255) / 256, 256, 0, s2>>>(Wih, Wihh, Wihl, G4 * Hd);
    k_split<<<(NNODE_ * Hd + 255) / 256, 256, 0, s2>>>(Wp, Wph, Wpl, NNODE_ * Hd);
    k_init_counts<<<Nn / 256, 256, 0, s2>>>(counts);
    k_count_edges<<<Ee / 256, 256, 0, s2>>>(ei, counts);
    k_scan16k<<<1, 1024, 0, s2>>>(counts, rowptr, cursor);
    k_scatter_edges<<<Ee / 256, 256, 0, s2>>>(ei, cursor, colsrc);
    k_scatter_loops<<<Nn / 256, 256, 0, s2>>>(cursor, colsrc);
    k_init_misc<<<(Bsz * Hd) / 256, 256, 0, s2>>>(len, bih, bhh, bsum, hS);
    k_count_len<<<Nn / 256, 256, 0, s2>>>(batch, len);
    k_scan256<<<1, Bsz, 0, s2>>>(len, starts);
    k_nodeidx<<<Nn / 256, 256, 0, s2>>>(batch, starts, nodeidx);
    cudaEventRecord(evJoin, s2);

    // ---- main stream continues in parallel ----
    k_gemm_bf3<<<dim3(F1 / GBN, Nn / GBM), 256, GEMM_SMEM>>>(
        x0h, x0l, W1Th, W1Tl, h1, Nn, F1, Hd, nullptr);
    k_alpha1<<<Nn, 256>>>(h1, attS1, attD1, as1, ad1);

    // ---- join: gat1 needs the CSR from s2 ----
    cudaStreamWaitEvent(0, evJoin, 0);

    k_gat1_agg<<<Nn, 256>>>(h1, as1, ad1, rowptr, colsrc, b1, x1h, x1l);

    k_gemm_bf3<<<dim3(Hd / GBN, Nn / GBM), 256, GEMM_SMEM>>>(
        x1h, x1l, W2Th, W2Tl, h2, Nn, Hd, F1, nullptr);

    k_alpha2<<<Nn, 256>>>(h2, attS2, attD2, as2, ad2);
    k_gat2_agg<<<Nn, 256>>>(h2, as2, ad2, rowptr, colsrc, b2, o2h, o2l);

    k_gemm_bf3<<<dim3(G4 / GBN, Nn / GBM), 256, GEMM_SMEM>>>(
        o2h, o2l, Wihh, Wihl, xg, Nn, G4, Hd, bsum);

    k_lstm<<<LSTM_BLOCKS, 256, LSTM_SMEM>>>(xg, nodeidx, len, hS, hb1, Whh);

    k_split<<<(Bsz * Hd + 255) / 256, 256>>>(hS, hTh, hTl, Bsz * Hd);
    k_gemm_bf3<<<dim3((NNODE_ + GBN - 1) / GBN, Bsz / GBM), 256, GEMM_SMEM>>>(
        hTh, hTl, Wph, Wpl, out, Bsz, NNODE_, Hd, bp);
}

// round 14
// speedup vs baseline: 1.1734x; 1.1181x over previous
#include <cuda_runtime.h>
#include <cuda_bf16.h>
#include <stdint.h>
#include <math.h>

typedef unsigned int u32;

// ---------------- problem constants ----------------
#define Nn      16384
#define Ee      131072
#define ETOT    (Ee + Nn)
#define Bsz     256
#define Lseq    64
#define Hd      256
#define NHEADS  8
#define F1      2048
#define G4      1024
#define NNODE_  37000

#define LSTM_BLOCKS 128

// ---------------- device scratch ----------------
__device__ float g_h1  [(size_t)Nn * F1];
__device__ float g_h2  [(size_t)Nn * Hd];
__device__ float g_xg  [(size_t)Nn * G4];
__device__ float g_as1 [Nn * NHEADS];
__device__ float g_ad1 [Nn * NHEADS];
__device__ float g_as2 [Nn];
__device__ float g_ad2 [Nn];
__device__ int   g_counts[Nn];
__device__ int   g_rowptr[Nn + 1];
__device__ int   g_cursor[Nn];
__device__ int   g_colsrc[ETOT];
__device__ int   g_len   [Bsz];
__device__ int   g_starts[Bsz];
__device__ int   g_nodeidx[Bsz * Lseq];
__device__ float g_hbuf1[Bsz * Hd];
__device__ float g_h    [Bsz * Hd];
__device__ float g_bsum [G4];
// per-mb-group barrier state: 8 groups, each on its own 128B line
__device__ unsigned g_grp_arrive[8 * 32];
__device__ unsigned g_grp_gen   [8 * 32];

// bf16 hi/lo split operands for tensor-core GEMMs
__device__ __nv_bfloat16 g_x0h[(size_t)Nn * Hd],  g_x0l[(size_t)Nn * Hd];
__device__ __nv_bfloat16 g_x1h[(size_t)Nn * F1],  g_x1l[(size_t)Nn * F1];
__device__ __nv_bfloat16 g_o2h[(size_t)Nn * Hd],  g_o2l[(size_t)Nn * Hd];
__device__ __nv_bfloat16 g_W1Th[(size_t)F1 * Hd], g_W1Tl[(size_t)F1 * Hd];
__device__ __nv_bfloat16 g_W2Th[(size_t)Hd * F1], g_W2Tl[(size_t)Hd * F1];
__device__ __nv_bfloat16 g_Wihh[(size_t)G4 * Hd], g_Wihl[(size_t)G4 * Hd];
__device__ __nv_bfloat16 g_hTh[Bsz * Hd],         g_hTl[Bsz * Hd];
__device__ __nv_bfloat16 g_Wph[(size_t)NNODE_ * Hd], g_Wpl[(size_t)NNODE_ * Hd];

// ---------------- small helpers ----------------
__device__ __forceinline__ void split_bf16(float v, __nv_bfloat16& h, __nv_bfloat16& l)
{
    h = __float2bfloat16(v);
    l = __float2bfloat16(v - __bfloat162float(h));
}
__device__ __forceinline__ u32 smem_u32(const void* p)
{
    return (u32)__cvta_generic_to_shared(p);
}
__device__ __forceinline__ void cp16(u32 dst, const void* src, int srcsize)
{
    asm volatile("cp.async.cg.shared.global [%0], [%1], 16, %2;"
                 :: "r"(dst), "l"(src), "r"(srcsize) : "memory");
}
__device__ __forceinline__ void cp_commit()
{
    asm volatile("cp.async.commit_group;" ::: "memory");
}
template<int NG>
__device__ __forceinline__ void cp_wait()
{
    asm volatile("cp.async.wait_group %0;" :: "n"(NG) : "memory");
}
__device__ __forceinline__ void ldsm_x4(u32 a, u32& r0, u32& r1, u32& r2, u32& r3)
{
    asm volatile("ldmatrix.sync.aligned.m8n8.x4.shared.b16 {%0,%1,%2,%3},[%4];"
                 : "=r"(r0), "=r"(r1), "=r"(r2), "=r"(r3) : "r"(a));
}
__device__ __forceinline__ void mma16816(float* c, u32 a0, u32 a1, u32 a2, u32 a3,
                                         u32 b0, u32 b1)
{
    asm volatile("mma.sync.aligned.m16n8k16.row.col.f32.bf16.bf16.f32 "
                 "{%0,%1,%2,%3},{%4,%5,%6,%7},{%8,%9},{%0,%1,%2,%3};"
                 : "+f"(c[0]), "+f"(c[1]), "+f"(c[2]), "+f"(c[3])
                 : "r"(a0), "r"(a1), "r"(a2), "r"(a3), "r"(b0), "r"(b1));
}

// ---------------- bf16x3 tensor-core GEMM (256 threads, 2 CTAs/SM) ----------------
#define GBM 128
#define GBN 128
#define GBK 32
#define BROW 40
#define ABUF (GBM * BROW)
#define GEMM_SMEM (8 * ABUF * 2)

__global__ void __launch_bounds__(256, 2)
k_gemm_bf3(const __nv_bfloat16* __restrict__ Ah, const __nv_bfloat16* __restrict__ Al,
           const __nv_bfloat16* __restrict__ Bh, const __nv_bfloat16* __restrict__ Bl,
           float* __restrict__ C, int M, int N, int K, const float* __restrict__ bias)
{
    extern __shared__ __nv_bfloat16 smg[];
    __nv_bfloat16* As = smg;
    __nv_bfloat16* Bs = smg + 4 * ABUF;
    const u32 sA = smem_u32(As);
    const u32 sB = smem_u32(Bs);

    const int tid  = threadIdx.x;
    const int bm   = blockIdx.y * GBM;
    const int bn   = blockIdx.x * GBN;
    const int warp = tid >> 5, lane = tid & 31;
    const int wm   = (warp >> 2) * 64;
    const int wn   = (warp & 3) * 32;

    float acc[4][4][4];
#pragma unroll
    for (int i = 0; i < 4; i++)
#pragma unroll
        for (int j = 0; j < 4; j++)
#pragma unroll
            for (int u = 0; u < 4; u++) acc[i][j][u] = 0.f;

    const int nstage = K / GBK;

    auto loadstage = [&](int kt, int st) {
        const int k0 = kt * GBK;
#pragma unroll
        for (int l = 0; l < 2; l++) {
            int i = tid + l * 256;
            int r = i >> 2, s = (i & 3) * 8;
            u32 doff = (u32)((r * BROW + s) * 2);
            size_t ga = (size_t)(bm + r) * K + k0 + s;
            cp16(sA + (u32)(st * 2 + 0) * (ABUF * 2) + doff, Ah + ga, 16);
            cp16(sA + (u32)(st * 2 + 1) * (ABUF * 2) + doff, Al + ga, 16);
            int nrow = bn + r;
            int ok = (nrow < N) ? 16 : 0;
            int nc = (nrow < N) ? nrow : (N - 1);
            size_t gb = (size_t)nc * K + k0 + s;
            cp16(sB + (u32)(st * 2 + 0) * (ABUF * 2) + doff, Bh + gb, ok);
            cp16(sB + (u32)(st * 2 + 1) * (ABUF * 2) + doff, Bl + gb, ok);
        }
        cp_commit();
    };

    loadstage(0, 0);
    int st = 0;
    for (int kt = 0; kt < nstage; kt++) {
        if (kt + 1 < nstage) { loadstage(kt + 1, st ^ 1); cp_wait<1>(); }
        else                 { cp_wait<0>(); }
        __syncthreads();

#pragma unroll
        for (int kk = 0; kk < 2; kk++) {
            u32 bfh[4][2], bfl[4][2];
#pragma unroll
            for (int half = 0; half < 2; half++) {
                int g = lane >> 3;
                u32 off = (u32)(((wn + half * 16 + (g & 1) * 8 + (lane & 7)) * BROW
                          + kk * 16 + (g >> 1) * 8) * 2);
                u32 r0, r1, r2, r3;
                ldsm_x4(sB + (u32)(st * 2 + 0) * (ABUF * 2) + off, r0, r1, r2, r3);
                bfh[half * 2 + 0][0] = r0; bfh[half * 2 + 1][0] = r1;
                bfh[half * 2 + 0][1] = r2; bfh[half * 2 + 1][1] = r3;
                ldsm_x4(sB + (u32)(st * 2 + 1) * (ABUF * 2) + off, r0, r1, r2, r3);
                bfl[half * 2 + 0][0] = r0; bfl[half * 2 + 1][0] = r1;
                bfl[half * 2 + 0][1] = r2; bfl[half * 2 + 1][1] = r3;
            }
#pragma unroll
            for (int mh = 0; mh < 2; mh++) {
                u32 afh[2][4], afl[2][4];
#pragma unroll
                for (int m2 = 0; m2 < 2; m2++) {
                    int mt = mh * 2 + m2;
                    u32 off = (u32)(((wm + mt * 16 + (lane & 15)) * BROW
                              + kk * 16 + (lane >> 4) * 8) * 2);
                    ldsm_x4(sA + (u32)(st * 2 + 0) * (ABUF * 2) + off,
                            afh[m2][0], afh[m2][1], afh[m2][2], afh[m2][3]);
                    ldsm_x4(sA + (u32)(st * 2 + 1) * (ABUF * 2) + off,
                            afl[m2][0], afl[m2][1], afl[m2][2], afl[m2][3]);
                }
#pragma unroll
                for (int m2 = 0; m2 < 2; m2++)
#pragma unroll
                    for (int nt = 0; nt < 4; nt++) {
                        float* a = acc[mh * 2 + m2][nt];
                        mma16816(a, afh[m2][0], afh[m2][1], afh[m2][2], afh[m2][3],
                                 bfh[nt][0], bfh[nt][1]);
                        mma16816(a, afh[m2][0], afh[m2][1], afh[m2][2], afh[m2][3],
                                 bfl[nt][0], bfl[nt][1]);
                        mma16816(a, afl[m2][0], afl[m2][1], afl[m2][2], afl[m2][3],
                                 bfh[nt][0], bfh[nt][1]);
                    }
            }
        }
        __syncthreads();
        st ^= 1;
    }

#pragma unroll
    for (int mt = 0; mt < 4; mt++) {
        int row0 = bm + wm + mt * 16 + (lane >> 2);
#pragma unroll
        for (int nt = 0; nt < 4; nt++) {
            int col = bn + wn + nt * 8 + (lane & 3) * 2;
            if (col < N) {
                float b0 = bias ? bias[col] : 0.f;
                float b1 = bias ? bias[col + 1] : 0.f;
                float2 v0 = make_float2(acc[mt][nt][0] + b0, acc[mt][nt][1] + b1);
                float2 v1 = make_float2(acc[mt][nt][2] + b0, acc[mt][nt][3] + b1);
                *reinterpret_cast<float2*>(&C[(size_t)row0 * N + col]) = v0;
                *reinterpret_cast<float2*>(&C[(size_t)(row0 + 8) * N + col]) = v1;
            }
        }
    }
}

// ---------------- split conversions ----------------
__global__ void k_split(const float* __restrict__ x, __nv_bfloat16* __restrict__ hi,
                        __nv_bfloat16* __restrict__ lo, int n)
{
    int i = blockIdx.x * blockDim.x + threadIdx.x;
    if (i < n) { __nv_bfloat16 h, l; split_bf16(x[i], h, l); hi[i] = h; lo[i] = l; }
}
__global__ void k_splitT(const float* __restrict__ W, __nv_bfloat16* __restrict__ hiT,
                         __nv_bfloat16* __restrict__ loT, int K, int N)
{
    __shared__ float tile[32][33];
    int k0 = blockIdx.y * 32, n0 = blockIdx.x * 32;
    int tx = threadIdx.x, ty = threadIdx.y;
    for (int i = ty; i < 32; i += 8)
        tile[i][tx] = W[(size_t)(k0 + i) * N + n0 + tx];
    __syncthreads();
    for (int i = ty; i < 32; i += 8) {
        float v = tile[tx][i];
        __nv_bfloat16 h, l; split_bf16(v, h, l);
        size_t o = (size_t)(n0 + i) * K + k0 + tx;
        hiT[o] = h; loT[o] = l;
    }
}

// ---------------- embedding gather + split ----------------
__global__ void k_gather_x0(const int* __restrict__ ids, const float* __restrict__ emb,
                            __nv_bfloat16* __restrict__ x0h, __nv_bfloat16* __restrict__ x0l)
{
    int i = blockIdx.x, t = threadIdx.x;
    int id = ids[i];
    float v = (id == 0) ? 0.f : emb[(size_t)id * Hd + t];
    __nv_bfloat16 h, l; split_bf16(v, h, l);
    x0h[(size_t)i * Hd + t] = h;
    x0l[(size_t)i * Hd + t] = l;
}

// ---------------- attention logits ----------------
__global__ void k_alpha1(const float* __restrict__ h1, const float* __restrict__ attS,
                         const float* __restrict__ attD,
                         float* __restrict__ outS, float* __restrict__ outD)
{
    int i = blockIdx.x;
    int w = threadIdx.x >> 5, lane = threadIdx.x & 31;
    const float* hp = h1 + (size_t)i * F1 + w * Hd;
    const float* ap = attS + w * Hd;
    const float* dp = attD + w * Hd;
    float ss = 0.f, sd = 0.f;
#pragma unroll
    for (int u = 0; u < 8; u++) {
        float v = hp[lane + 32 * u];
        ss += v * ap[lane + 32 * u];
        sd += v * dp[lane + 32 * u];
    }
#pragma unroll
    for (int o = 16; o; o >>= 1) {
        ss += __shfl_xor_sync(0xffffffffu, ss, o);
        sd += __shfl_xor_sync(0xffffffffu, sd, o);
    }
    if (lane == 0) { outS[i * NHEADS + w] = ss; outD[i * NHEADS + w] = sd; }
}

__global__ void k_alpha2(const float* __restrict__ h2, const float* __restrict__ attS,
                         const float* __restrict__ attD,
                         float* __restrict__ outS, float* __restrict__ outD)
{
    __shared__ float shS[8], shD[8];
    int i = blockIdx.x, t = threadIdx.x;
    float v = h2[(size_t)i * Hd + t];
    float ss = v * attS[t], sd = v * attD[t];
    int lane = t & 31, w = t >> 5;
#pragma unroll
    for (int o = 16; o; o >>= 1) {
        ss += __shfl_xor_sync(0xffffffffu, ss, o);
        sd += __shfl_xor_sync(0xffffffffu, sd, o);
    }
    if (lane == 0) { shS[w] = ss; shD[w] = sd; }
    __syncthreads();
    if (t == 0) {
        float a = 0.f, b = 0.f;
#pragma unroll
        for (int u = 0; u < 8; u++) { a += shS[u]; b += shD[u]; }
        outS[i] = a; outD[i] = b;
    }
}

// ---------------- CSR build ----------------
__global__ void k_init_counts(int* __restrict__ counts)
{
    int i = blockIdx.x * blockDim.x + threadIdx.x;
    if (i < Nn) counts[i] = 1;
}
__global__ void k_count_edges(const int* __restrict__ ei, int* __restrict__ counts)
{
    int e = blockIdx.x * blockDim.x + threadIdx.x;
    if (e < Ee) atomicAdd(&counts[ei[Ee + e]], 1);
}
__global__ void k_scan16k(const int* __restrict__ counts, int* __restrict__ rowptr,
                          int* __restrict__ cursor)
{
    __shared__ int wsum[32];
    const int tid = threadIdx.x;
    const int per = Nn / 1024;
    const int base = tid * per;
    int c[16];
    int tot = 0;
#pragma unroll
    for (int u = 0; u < per; u++) { c[u] = counts[base + u]; tot += c[u]; }
    int lane = tid & 31, wid = tid >> 5;
    int v = tot;
#pragma unroll
    for (int o = 1; o < 32; o <<= 1) {
        int t2 = __shfl_up_sync(0xffffffffu, v, o);
        if (lane >= o) v += t2;
    }
    if (lane == 31) wsum[wid] = v;
    __syncthreads();
    if (wid == 0) {
        int w = wsum[lane];
#pragma unroll
        for (int o = 1; o < 32; o <<= 1) {
            int t2 = __shfl_up_sync(0xffffffffu, w, o);
            if (lane >= o) w += t2;
        }
        wsum[lane] = w;
    }
    __syncthreads();
    int run = (v - tot) + (wid > 0 ? wsum[wid - 1] : 0);
#pragma unroll
    for (int u = 0; u < per; u++) {
        rowptr[base + u] = run;
        cursor[base + u] = run;
        run += c[u];
    }
    if (tid == 1023) rowptr[Nn] = run;
}
__global__ void k_scatter_edges(const int* __restrict__ ei,
                                int* __restrict__ cursor, int* __restrict__ colsrc)
{
    int e = blockIdx.x * blockDim.x + threadIdx.x;
    if (e < Ee) {
        int d = ei[Ee + e];
        int p = atomicAdd(&cursor[d], 1);
        colsrc[p] = ei[e];
    }
}
__global__ void k_scatter_loops(int* __restrict__ cursor, int* __restrict__ colsrc)
{
    int i = blockIdx.x * blockDim.x + threadIdx.x;
    if (i < Nn) {
        int p = atomicAdd(&cursor[i], 1);
        colsrc[p] = i;
    }
}

// ---------------- GAT aggregation (two-pass softmax, fused bf16 split) ----------------
__global__ void k_gat1_agg(const float* __restrict__ h1,
                           const float* __restrict__ aS, const float* __restrict__ aD,
                           const int* __restrict__ rowptr, const int* __restrict__ colsrc,
                           const float* __restrict__ b1,
                           __nv_bfloat16* __restrict__ x1h, __nv_bfloat16* __restrict__ x1l)
{
    int dst = blockIdx.x;
    int w = threadIdx.x >> 5, lane = threadIdx.x & 31;
    int beg = rowptr[dst], end = rowptr[dst + 1];
    float adv = aD[dst * NHEADS + w];

    float m = -3.4e38f;
    for (int e = beg; e < end; e++) {
        float v = aS[colsrc[e] * NHEADS + w] + adv;
        v = v > 0.f ? v : 0.2f * v;
        m = fmaxf(m, v);
    }
    float acc[8] = {0.f, 0.f, 0.f, 0.f, 0.f, 0.f, 0.f, 0.f};
    float sump = 0.f;
    for (int e = beg; e < end; e++) {
        int s = colsrc[e];
        float v = aS[s * NHEADS + w] + adv;
        v = v > 0.f ? v : 0.2f * v;
        float p = expf(v - m);
        sump += p;
        const float* hp = h1 + (size_t)s * F1 + w * Hd + lane;
#pragma unroll
        for (int u = 0; u < 8; u++) acc[u] += p * hp[u * 32];
    }
    float inv = 1.f / (sump + 1e-16f);
    size_t base = (size_t)dst * F1 + w * Hd + lane;
    const float* bp = b1 + w * Hd + lane;
#pragma unroll
    for (int u = 0; u < 8; u++) {
        float o = acc[u] * inv + bp[u * 32];
        o = o > 0.f ? o : expm1f(o);           // ELU
        __nv_bfloat16 h, l; split_bf16(o, h, l);
        x1h[base + u * 32] = h;
        x1l[base + u * 32] = l;
    }
}

__global__ void k_gat2_agg(const float* __restrict__ h2,
                           const float* __restrict__ aS, const float* __restrict__ aD,
                           const int* __restrict__ rowptr, const int* __restrict__ colsrc,
                           const float* __restrict__ b2,
                           __nv_bfloat16* __restrict__ o2h, __nv_bfloat16* __restrict__ o2l)
{
    int dst = blockIdx.x, t = threadIdx.x;
    int beg = rowptr[dst], end = rowptr[dst + 1];
    float adv = aD[dst];
    float m = -3.4e38f;
    for (int e = beg; e < end; e++) {
        float v = aS[colsrc[e]] + adv;
        v = v > 0.f ? v : 0.2f * v;
        m = fmaxf(m, v);
    }
    float acc = 0.f, sump = 0.f;
    for (int e = beg; e < end; e++) {
        int s = colsrc[e];
        float v = aS[s] + adv;
        v = v > 0.f ? v : 0.2f * v;
        float p = expf(v - m);
        sump += p;
        acc += p * h2[(size_t)s * Hd + t];
    }
    float o = acc / (sump + 1e-16f) + b2[t];
    __nv_bfloat16 h, l; split_bf16(o, h, l);
    o2h[(size_t)dst * Hd + t] = h;
    o2l[(size_t)dst * Hd + t] = l;
}

// ---------------- sequence bookkeeping ----------------
__global__ void k_init_misc(int* __restrict__ len, const float* __restrict__ bih,
                            const float* __restrict__ bhh, float* __restrict__ bs,
                            float* __restrict__ h)
{
    int i = blockIdx.x * blockDim.x + threadIdx.x;
    if (i < Bsz) len[i] = 0;
    if (i < G4) bs[i] = bih[i] + bhh[i];
    h[i] = 0.f;
}
__global__ void k_count_len(const int* __restrict__ batch, int* __restrict__ len)
{
    int i = blockIdx.x * blockDim.x + threadIdx.x;
    if (i < Nn) atomicAdd(&len[batch[i]], 1);
}
__global__ void k_scan256(const int* __restrict__ len, int* __restrict__ starts)
{
    __shared__ int wsum[8];
    int tid = threadIdx.x;
    int orig = len[tid];
    int v = orig;
    int lane = tid & 31, wid = tid >> 5;
#pragma unroll
    for (int o = 1; o < 32; o <<= 1) {
        int t2 = __shfl_up_sync(0xffffffffu, v, o);
        if (lane >= o) v += t2;
    }
    if (lane == 31) wsum[wid] = v;
    __syncthreads();
    if (tid == 0) {
        int s = 0;
#pragma unroll
        for (int u = 0; u < 8; u++) { int t2 = wsum[u]; wsum[u] = s; s += t2; }
    }
    __syncthreads();
    starts[tid] = (v - orig) + wsum[wid];
}
__global__ void k_nodeidx(const int* __restrict__ batch, const int* __restrict__ starts,
                          int* __restrict__ nodeidx)
{
    int i = blockIdx.x * blockDim.x + threadIdx.x;
    if (i < Nn) {
        int b = batch[i];
        int p = i - starts[b];
        if (p >= 0 && p < Lseq) nodeidx[b * Lseq + p] = i;
    }
}

// ---------------- persistent fused LSTM (tensor-core bf16x3 step GEMM) ----------------
// Block (jb, mb): 16 hidden units (64 gate rows), 32 batches. 8 warps:
// mw = warp>>1 (gate tile, 16 rows), nw = warp&1 (batch half, 16).
// Whh slice split hi/lo to smem once (ldmatrix layout, row stride LW bf16).
// Each step: load h fp32 (exact copy kept in Hprev), split to bf16 tiles,
// MMA 64x32x256 (3-term bf16x3), gates staged via smem, combine as before.
#define LW 264                     // bf16 elems per row (528B = 33*16B, LDSM conflict-free)
#define HPW 260                    // Hprev fp32 row stride
#define GSW 33                     // gate smem row stride (floats)
#define LSTM_SMEM_BYTES ((2*64*LW + 2*32*LW) * 2 + (32*HPW + 64*GSW + 512) * 4)

__global__ void __launch_bounds__(256, 1)
k_lstm(const float* __restrict__ xg, const int* __restrict__ nodeidx,
       const int* __restrict__ len, float* __restrict__ hbuf0,
       float* __restrict__ hbuf1, const float* __restrict__ Whh)
{
    extern __shared__ char smB[];
    __nv_bfloat16* WshH = (__nv_bfloat16*)smB;          // [64][LW]
    __nv_bfloat16* WshL = WshH + 64 * LW;               // [64][LW]
    __nv_bfloat16* HshH = WshL + 64 * LW;               // [32][LW]
    __nv_bfloat16* HshL = HshH + 32 * LW;               // [32][LW]
    float* Hprev = (float*)(HshL + 32 * LW);            // [32][HPW]
    float* gsh   = Hprev + 32 * HPW;                    // [64][GSW]
    float* csh   = gsh + 64 * GSW;                      // [16][32]

    const int tid  = threadIdx.x;
    const int jb   = blockIdx.x & 15;
    const int mb   = blockIdx.x >> 4;
    const int warp = tid >> 5, lane = tid & 31;
    const int mw   = warp >> 1;          // gate tile (0..3)
    const int nw   = warp & 1;           // batch half (0..1)

    unsigned* grp_arr = &g_grp_arrive[mb * 32];
    unsigned* grp_gen = &g_grp_gen[mb * 32];
    unsigned my_gen = atomicAdd(grp_gen, 0u);

    // one-time: Whh slice -> bf16 hi/lo smem. local row r = g*16+u <-> global g*256 + jb*16 + u
    for (int idx = tid; idx < 64 * 256; idx += 256) {
        int r = idx >> 8;
        int k = idx & 255;
        int g = r >> 4, u = r & 15;
        float v = Whh[(size_t)(g * 256 + jb * 16 + u) * 256 + k];
        __nv_bfloat16 h, l; split_bf16(v, h, l);
        WshH[r * LW + k] = h;
        WshL[r * LW + k] = l;
    }
    if (tid < 256) { csh[tid] = 0.f; csh[tid + 256] = 0.f; }

    const u32 sWH = smem_u32(WshH);
    const u32 sWL = smem_u32(WshL);
    const u32 sHH = smem_u32(HshH);
    const u32 sHL = smem_u32(HshL);

    for (int t = 0; t < Lseq; t++) {
        // ---- load h_cur fp32 + split to bf16 tiles (8 float4 per thread) ----
        const float* hc = (t & 1) ? hbuf1 : hbuf0;
#pragma unroll
        for (int l = 0; l < 8; l++) {
            int i4 = tid + l * 256;              // 0..2047
            int bl = i4 >> 6;                    // batch 0..31
            int k4 = (i4 & 63) * 4;              // k 0..252
            float4 v = *(const float4*)&hc[(size_t)(mb * 32 + bl) * 256 + k4];
            *(float4*)&Hprev[bl * HPW + k4] = v;
            __nv_bfloat16 h0, l0, h1b, l1b, h2b, l2b, h3b, l3b;
            split_bf16(v.x, h0, l0);  split_bf16(v.y, h1b, l1b);
            split_bf16(v.z, h2b, l2b); split_bf16(v.w, h3b, l3b);
            __nv_bfloat16* ph = &HshH[bl * LW + k4];
            __nv_bfloat16* pl = &HshL[bl * LW + k4];
            ph[0] = h0; ph[1] = h1b; ph[2] = h2b; ph[3] = h3b;
            pl[0] = l0; pl[1] = l1b; pl[2] = l2b; pl[3] = l3b;
        }
        __syncthreads();

        // ---- MMA: gates[64][32] = W[64][256] @ h[32][256]^T (bf16x3) ----
        float acc[2][4];
#pragma unroll
        for (int nt = 0; nt < 2; nt++)
#pragma unroll
            for (int u = 0; u < 4; u++) acc[nt][u] = 0.f;

#pragma unroll
        for (int ks = 0; ks < 16; ks++) {
            const int kb = ks * 16;
            // A fragments (16 rows x 16 k)
            u32 aoff = (u32)(((mw * 16 + (lane & 15)) * LW + kb + (lane >> 4) * 8) * 2);
            u32 ah0, ah1, ah2, ah3, al0, al1, al2, al3;
            ldsm_x4(sWH + aoff, ah0, ah1, ah2, ah3);
            ldsm_x4(sWL + aoff, al0, al1, al2, al3);
            // B fragments (16 batches covering both 8-wide n-tiles)
            int g = lane >> 3;
            u32 boff = (u32)(((nw * 16 + (g & 1) * 8 + (lane & 7)) * LW + kb + (g >> 1) * 8) * 2);
            u32 r0, r1, r2, r3;
            u32 bh[2][2], blo[2][2];
            ldsm_x4(sHH + boff, r0, r1, r2, r3);
            bh[0][0] = r0; bh[1][0] = r1; bh[0][1] = r2; bh[1][1] = r3;
            ldsm_x4(sHL + boff, r0, r1, r2, r3);
            blo[0][0] = r0; blo[1][0] = r1; blo[0][1] = r2; blo[1][1] = r3;
#pragma unroll
            for (int nt = 0; nt < 2; nt++) {
                mma16816(acc[nt], ah0, ah1, ah2, ah3, bh[nt][0], bh[nt][1]);
                mma16816(acc[nt], ah0, ah1, ah2, ah3, blo[nt][0], blo[nt][1]);
                mma16816(acc[nt], al0, al1, al2, al3, bh[nt][0], bh[nt][1]);
            }
        }

        // ---- stage gates to smem: C row = gate row, col = batch ----
        {
            int grow = mw * 16 + (lane >> 2);
#pragma unroll
            for (int nt = 0; nt < 2; nt++) {
                int col = nw * 16 + nt * 8 + (lane & 3) * 2;
                gsh[grow * GSW + col]           = acc[nt][0];
                gsh[grow * GSW + col + 1]       = acc[nt][1];
                gsh[(grow + 8) * GSW + col]     = acc[nt][2];
                gsh[(grow + 8) * GSW + col + 1] = acc[nt][3];
            }
        }
        __syncthreads();

        // ---- combine: + xg, gates, update c (smem) & h (global) ----
        float* hn_buf = (t & 1) ? hbuf0 : hbuf1;
#pragma unroll
        for (int p = tid; p < 512; p += 256) {
            int u = p & 15;
            int bl = p >> 4;
            int bglob = mb * 32 + bl;
            int node = nodeidx[bglob * Lseq + t];
            const float* xp = xg + (size_t)node * G4 + jb * 16 + u;
            float gi = gsh[(0  + u) * GSW + bl] + xp[0];
            float gf = gsh[(16 + u) * GSW + bl] + xp[256];
            float gg = gsh[(32 + u) * GSW + bl] + xp[512];
            float go = gsh[(48 + u) * GSW + bl] + xp[768];
            float hprev = Hprev[bl * HPW + jb * 16 + u];
            float cprev = csh[u * 32 + bl];
            float si = 1.f / (1.f + expf(-gi));
            float sf = 1.f / (1.f + expf(-gf));
            float so = 1.f / (1.f + expf(-go));
            float cn = sf * cprev + si * tanhf(gg);
            float hn = so * tanhf(cn);
            bool act = (t < len[bglob]);
            if (act) csh[u * 32 + bl] = cn;
            float hw = act ? hn : hprev;
            __stcg(&hn_buf[bglob * 256 + jb * 16 + u], hw);
        }

        if (t != Lseq - 1) {
            __threadfence();
            __syncthreads();
            if (tid == 0) {
                unsigned old = atomicAdd(grp_arr, 1u);
                if (old == 15u) {
                    atomicExch(grp_arr, 0u);
                    __threadfence();
                    atomicAdd(grp_gen, 1u);
                } else {
                    while (atomicAdd(grp_gen, 0u) == my_gen) { }
                }
            }
            __syncthreads();
            my_gen++;
        }
    }
}

// ---------------- host launcher ----------------
extern "C" void kernel_launch(void* const* d_in, const int* in_sizes, int n_in,
                              void* d_out, int out_size)
{
    const int*   x_ids = (const int*)d_in[0];
    const int*   ei    = (const int*)d_in[1];
    const int*   batch = (const int*)d_in[2];
    const float* emb   = (const float*)d_in[3];
    const float* W1    = (const float*)d_in[4];
    const float* attS1 = (const float*)d_in[5];
    const float* attD1 = (const float*)d_in[6];
    const float* b1    = (const float*)d_in[7];
    const float* W2    = (const float*)d_in[8];
    const float* attS2 = (const float*)d_in[9];
    const float* attD2 = (const float*)d_in[10];
    const float* b2    = (const float*)d_in[11];
    const float* Wih   = (const float*)d_in[12];
    const float* Whh   = (const float*)d_in[13];
    const float* bih   = (const float*)d_in[14];
    const float* bhh   = (const float*)d_in[15];
    const float* Wp    = (const float*)d_in[16];
    const float* bp    = (const float*)d_in[17];
    float* out = (float*)d_out;

    void* p;
    cudaGetSymbolAddress(&p, g_h1);      float* h1   = (float*)p;
    cudaGetSymbolAddress(&p, g_h2);      float* h2   = (float*)p;
    cudaGetSymbolAddress(&p, g_xg);      float* xg   = (float*)p;
    cudaGetSymbolAddress(&p, g_as1);     float* as1  = (float*)p;
    cudaGetSymbolAddress(&p, g_ad1);     float* ad1  = (float*)p;
    cudaGetSymbolAddress(&p, g_as2);     float* as2  = (float*)p;
    cudaGetSymbolAddress(&p, g_ad2);     float* ad2  = (float*)p;
    cudaGetSymbolAddress(&p, g_counts);  int* counts = (int*)p;
    cudaGetSymbolAddress(&p, g_rowptr);  int* rowptr = (int*)p;
    cudaGetSymbolAddress(&p, g_cursor);  int* cursor = (int*)p;
    cudaGetSymbolAddress(&p, g_colsrc);  int* colsrc = (int*)p;
    cudaGetSymbolAddress(&p, g_len);     int* len    = (int*)p;
    cudaGetSymbolAddress(&p, g_starts);  int* starts = (int*)p;
    cudaGetSymbolAddress(&p, g_nodeidx); int* nodeidx= (int*)p;
    cudaGetSymbolAddress(&p, g_hbuf1);   float* hb1  = (float*)p;
    cudaGetSymbolAddress(&p, g_h);       float* hS   = (float*)p;
    cudaGetSymbolAddress(&p, g_bsum);    float* bsum = (float*)p;

    __nv_bfloat16 *x0h, *x0l, *x1h, *x1l, *o2h, *o2l;
    __nv_bfloat16 *W1Th, *W1Tl, *W2Th, *W2Tl, *Wihh, *Wihl, *hTh, *hTl, *Wph, *Wpl;
    cudaGetSymbolAddress(&p, g_x0h); x0h = (__nv_bfloat16*)p;
    cudaGetSymbolAddress(&p, g_x0l); x0l = (__nv_bfloat16*)p;
    cudaGetSymbolAddress(&p, g_x1h); x1h = (__nv_bfloat16*)p;
    cudaGetSymbolAddress(&p, g_x1l); x1l = (__nv_bfloat16*)p;
    cudaGetSymbolAddress(&p, g_o2h); o2h = (__nv_bfloat16*)p;
    cudaGetSymbolAddress(&p, g_o2l); o2l = (__nv_bfloat16*)p;
    cudaGetSymbolAddress(&p, g_W1Th); W1Th = (__nv_bfloat16*)p;
    cudaGetSymbolAddress(&p, g_W1Tl); W1Tl = (__nv_bfloat16*)p;
    cudaGetSymbolAddress(&p, g_W2Th); W2Th = (__nv_bfloat16*)p;
    cudaGetSymbolAddress(&p, g_W2Tl); W2Tl = (__nv_bfloat16*)p;
    cudaGetSymbolAddress(&p, g_Wihh); Wihh = (__nv_bfloat16*)p;
    cudaGetSymbolAddress(&p, g_Wihl); Wihl = (__nv_bfloat16*)p;
    cudaGetSymbolAddress(&p, g_hTh);  hTh  = (__nv_bfloat16*)p;
    cudaGetSymbolAddress(&p, g_hTl);  hTl  = (__nv_bfloat16*)p;
    cudaGetSymbolAddress(&p, g_Wph);  Wph  = (__nv_bfloat16*)p;
    cudaGetSymbolAddress(&p, g_Wpl);  Wpl  = (__nv_bfloat16*)p;

    cudaFuncSetAttribute(k_lstm, cudaFuncAttributeMaxDynamicSharedMemorySize, LSTM_SMEM_BYTES);
    cudaFuncSetAttribute(k_gemm_bf3, cudaFuncAttributeMaxDynamicSharedMemorySize, GEMM_SMEM);

    cudaStream_t s2;
    cudaStreamCreateWithFlags(&s2, cudaStreamNonBlocking);
    cudaEvent_t evFork, evJoin;
    cudaEventCreateWithFlags(&evFork, cudaEventDisableTiming);
    cudaEventCreateWithFlags(&evJoin, cudaEventDisableTiming);

    // ---- main stream: GEMM1 dependency chain ----
    k_gather_x0<<<Nn, Hd>>>(x_ids, emb, x0h, x0l);
    k_splitT<<<dim3(F1 / 32, Hd / 32), dim3(32, 8)>>>(W1, W1Th, W1Tl, Hd, F1);

    // ---- fork: all GEMM1-independent prep on s2 ----
    cudaEventRecord(evFork, 0);
    cudaStreamWaitEvent(s2, evFork, 0);
    k_splitT<<<dim3(Hd / 32, F1 / 32), dim3(32, 8), 0, s2>>>(W2, W2Th, W2Tl, F1, Hd);
    k_split<<<(G4 * Hd + 255) / 256, 256, 0, s2>>>(Wih, Wihh, Wihl, G4 * Hd);
    k_split<<<(NNODE_ * Hd + 255) / 256, 256, 0, s2>>>(Wp, Wph, Wpl, NNODE_ * Hd);
    k_init_counts<<<Nn / 256, 256, 0, s2>>>(counts);
    k_count_edges<<<Ee / 256, 256, 0, s2>>>(ei, counts);
    k_scan16k<<<1, 1024, 0, s2>>>(counts, rowptr, cursor);
    k_scatter_edges<<<Ee / 256, 256, 0, s2>>>(ei, cursor, colsrc);
    k_scatter_loops<<<Nn / 256, 256, 0, s2>>>(cursor, colsrc);
    k_init_misc<<<(Bsz * Hd) / 256, 256, 0, s2>>>(len, bih, bhh, bsum, hS);
    k_count_len<<<Nn / 256, 256, 0, s2>>>(batch, len);
    k_scan256<<<1, Bsz, 0, s2>>>(len, starts);
    k_nodeidx<<<Nn / 256, 256, 0, s2>>>(batch, starts, nodeidx);
    cudaEventRecord(evJoin, s2);

    // ---- main stream continues in parallel ----
    k_gemm_bf3<<<dim3(F1 / GBN, Nn / GBM), 256, GEMM_SMEM>>>(
        x0h, x0l, W1Th, W1Tl, h1, Nn, F1, Hd, nullptr);
    k_alpha1<<<Nn, 256>>>(h1, attS1, attD1, as1, ad1);

    // ---- join: gat1 needs the CSR from s2 ----
    cudaStreamWaitEvent(0, evJoin, 0);

    k_gat1_agg<<<Nn, 256>>>(h1, as1, ad1, rowptr, colsrc, b1, x1h, x1l);

    k_gemm_bf3<<<dim3(Hd / GBN, Nn / GBM), 256, GEMM_SMEM>>>(
        x1h, x1l, W2Th, W2Tl, h2, Nn, Hd, F1, nullptr);

    k_alpha2<<<Nn, 256>>>(h2, attS2, attD2, as2, ad2);
    k_gat2_agg<<<Nn, 256>>>(h2, as2, ad2, rowptr, colsrc, b2, o2h, o2l);

    k_gemm_bf3<<<dim3(G4 / GBN, Nn / GBM), 256, GEMM_SMEM>>>(
        o2h, o2l, Wihh, Wihl, xg, Nn, G4, Hd, bsum);

    k_lstm<<<LSTM_BLOCKS, 256, LSTM_SMEM_BYTES>>>(xg, nodeidx, len, hS, hb1, Whh);

    k_split<<<(Bsz * Hd + 255) / 256, 256>>>(hS, hTh, hTl, Bsz * Hd);
    k_gemm_bf3<<<dim3((NNODE_ + GBN - 1) / GBN, Bsz / GBM), 256, GEMM_SMEM>>>(
        hTh, hTl, Wph, Wpl, out, Bsz, NNODE_, Hd, bp);
}

// round 15
// speedup vs baseline: 1.1794x; 1.0051x over previous
#include <cuda_runtime.h>
#include <cuda_bf16.h>
#include <stdint.h>
#include <math.h>

typedef unsigned int u32;

// ---------------- problem constants ----------------
#define Nn      16384
#define Ee      131072
#define ETOT    (Ee + Nn)
#define Bsz     256
#define Lseq    64
#define Hd      256
#define NHEADS  8
#define F1      2048
#define G4      1024
#define NNODE_  37000

#define LSTM_BLOCKS 128

// ---------------- device scratch ----------------
__device__ float g_h1  [(size_t)Nn * F1];
__device__ float g_h2  [(size_t)Nn * Hd];
__device__ float g_xg  [(size_t)Nn * G4];
__device__ float g_as1 [Nn * NHEADS];
__device__ float g_ad1 [Nn * NHEADS];
__device__ float g_as2 [Nn];
__device__ float g_ad2 [Nn];
__device__ int   g_counts[Nn];
__device__ int   g_rowptr[Nn + 1];
__device__ int   g_cursor[Nn];
__device__ int   g_colsrc[ETOT];
__device__ int   g_len   [Bsz];
__device__ int   g_starts[Bsz];
__device__ int   g_nodeidx[Bsz * Lseq];
__device__ float g_hbuf1[Bsz * Hd];
__device__ float g_h    [Bsz * Hd];
__device__ float g_bsum [G4];
// per-mb-group barrier state: 8 groups, each on its own 128B line
__device__ unsigned g_grp_arrive[8 * 32];
__device__ unsigned g_grp_gen   [8 * 32];

// bf16 hi/lo split operands for tensor-core GEMMs
__device__ __nv_bfloat16 g_x0h[(size_t)Nn * Hd],  g_x0l[(size_t)Nn * Hd];
__device__ __nv_bfloat16 g_x1h[(size_t)Nn * F1],  g_x1l[(size_t)Nn * F1];
__device__ __nv_bfloat16 g_o2h[(size_t)Nn * Hd],  g_o2l[(size_t)Nn * Hd];
__device__ __nv_bfloat16 g_W1Th[(size_t)F1 * Hd], g_W1Tl[(size_t)F1 * Hd];
__device__ __nv_bfloat16 g_W2Th[(size_t)Hd * F1], g_W2Tl[(size_t)Hd * F1];
__device__ __nv_bfloat16 g_Wihh[(size_t)G4 * Hd], g_Wihl[(size_t)G4 * Hd];
__device__ __nv_bfloat16 g_hTh[Bsz * Hd],         g_hTl[Bsz * Hd];
__device__ __nv_bfloat16 g_Wph[(size_t)NNODE_ * Hd], g_Wpl[(size_t)NNODE_ * Hd];

// ---------------- small helpers ----------------
__device__ __forceinline__ void split_bf16(float v, __nv_bfloat16& h, __nv_bfloat16& l)
{
    h = __float2bfloat16(v);
    l = __float2bfloat16(v - __bfloat162float(h));
}
__device__ __forceinline__ u32 smem_u32(const void* p)
{
    return (u32)__cvta_generic_to_shared(p);
}
__device__ __forceinline__ void cp16(u32 dst, const void* src, int srcsize)
{
    asm volatile("cp.async.cg.shared.global [%0], [%1], 16, %2;"
                 :: "r"(dst), "l"(src), "r"(srcsize) : "memory");
}
__device__ __forceinline__ void cp_commit()
{
    asm volatile("cp.async.commit_group;" ::: "memory");
}
template<int NG>
__device__ __forceinline__ void cp_wait()
{
    asm volatile("cp.async.wait_group %0;" :: "n"(NG) : "memory");
}
__device__ __forceinline__ void ldsm_x4(u32 a, u32& r0, u32& r1, u32& r2, u32& r3)
{
    asm volatile("ldmatrix.sync.aligned.m8n8.x4.shared.b16 {%0,%1,%2,%3},[%4];"
                 : "=r"(r0), "=r"(r1), "=r"(r2), "=r"(r3) : "r"(a));
}
__device__ __forceinline__ void mma16816(float* c, u32 a0, u32 a1, u32 a2, u32 a3,
                                         u32 b0, u32 b1)
{
    asm volatile("mma.sync.aligned.m16n8k16.row.col.f32.bf16.bf16.f32 "
                 "{%0,%1,%2,%3},{%4,%5,%6,%7},{%8,%9},{%0,%1,%2,%3};"
                 : "+f"(c[0]), "+f"(c[1]), "+f"(c[2]), "+f"(c[3])
                 : "r"(a0), "r"(a1), "r"(a2), "r"(a3), "r"(b0), "r"(b1));
}

// ---------------- bf16x3 tensor-core GEMM (256 threads, 2 CTAs/SM) ----------------
// Optional fused attention-logit epilogue: outS[row*nh + col>>8] += C[row][col]*attS[col]
// (flat att index == col because att_src is (heads,256) contiguous and headsz==256).
#define GBM 128
#define GBN 128
#define GBK 32
#define BROW 40
#define ABUF (GBM * BROW)
#define GEMM_SMEM (8 * ABUF * 2)

__global__ void __launch_bounds__(256, 2)
k_gemm_bf3(const __nv_bfloat16* __restrict__ Ah, const __nv_bfloat16* __restrict__ Al,
           const __nv_bfloat16* __restrict__ Bh, const __nv_bfloat16* __restrict__ Bl,
           float* __restrict__ C, int M, int N, int K, const float* __restrict__ bias,
           const float* __restrict__ attS, const float* __restrict__ attD,
           float* __restrict__ outS, float* __restrict__ outD, int nh)
{
    extern __shared__ __nv_bfloat16 smg[];
    __nv_bfloat16* As = smg;
    __nv_bfloat16* Bs = smg + 4 * ABUF;
    const u32 sA = smem_u32(As);
    const u32 sB = smem_u32(Bs);

    const int tid  = threadIdx.x;
    const int bm   = blockIdx.y * GBM;
    const int bn   = blockIdx.x * GBN;
    const int warp = tid >> 5, lane = tid & 31;
    const int wm   = (warp >> 2) * 64;
    const int wn   = (warp & 3) * 32;

    float acc[4][4][4];
#pragma unroll
    for (int i = 0; i < 4; i++)
#pragma unroll
        for (int j = 0; j < 4; j++)
#pragma unroll
            for (int u = 0; u < 4; u++) acc[i][j][u] = 0.f;

    const int nstage = K / GBK;

    auto loadstage = [&](int kt, int st) {
        const int k0 = kt * GBK;
#pragma unroll
        for (int l = 0; l < 2; l++) {
            int i = tid + l * 256;
            int r = i >> 2, s = (i & 3) * 8;
            u32 doff = (u32)((r * BROW + s) * 2);
            size_t ga = (size_t)(bm + r) * K + k0 + s;
            cp16(sA + (u32)(st * 2 + 0) * (ABUF * 2) + doff, Ah + ga, 16);
            cp16(sA + (u32)(st * 2 + 1) * (ABUF * 2) + doff, Al + ga, 16);
            int nrow = bn + r;
            int ok = (nrow < N) ? 16 : 0;
            int nc = (nrow < N) ? nrow : (N - 1);
            size_t gb = (size_t)nc * K + k0 + s;
            cp16(sB + (u32)(st * 2 + 0) * (ABUF * 2) + doff, Bh + gb, ok);
            cp16(sB + (u32)(st * 2 + 1) * (ABUF * 2) + doff, Bl + gb, ok);
        }
        cp_commit();
    };

    loadstage(0, 0);
    int st = 0;
    for (int kt = 0; kt < nstage; kt++) {
        if (kt + 1 < nstage) { loadstage(kt + 1, st ^ 1); cp_wait<1>(); }
        else                 { cp_wait<0>(); }
        __syncthreads();

#pragma unroll
        for (int kk = 0; kk < 2; kk++) {
            u32 bfh[4][2], bfl[4][2];
#pragma unroll
            for (int half = 0; half < 2; half++) {
                int g = lane >> 3;
                u32 off = (u32)(((wn + half * 16 + (g & 1) * 8 + (lane & 7)) * BROW
                          + kk * 16 + (g >> 1) * 8) * 2);
                u32 r0, r1, r2, r3;
                ldsm_x4(sB + (u32)(st * 2 + 0) * (ABUF * 2) + off, r0, r1, r2, r3);
                bfh[half * 2 + 0][0] = r0; bfh[half * 2 + 1][0] = r1;
                bfh[half * 2 + 0][1] = r2; bfh[half * 2 + 1][1] = r3;
                ldsm_x4(sB + (u32)(st * 2 + 1) * (ABUF * 2) + off, r0, r1, r2, r3);
                bfl[half * 2 + 0][0] = r0; bfl[half * 2 + 1][0] = r1;
                bfl[half * 2 + 0][1] = r2; bfl[half * 2 + 1][1] = r3;
            }
#pragma unroll
            for (int mh = 0; mh < 2; mh++) {
                u32 afh[2][4], afl[2][4];
#pragma unroll
                for (int m2 = 0; m2 < 2; m2++) {
                    int mt = mh * 2 + m2;
                    u32 off = (u32)(((wm + mt * 16 + (lane & 15)) * BROW
                              + kk * 16 + (lane >> 4) * 8) * 2);
                    ldsm_x4(sA + (u32)(st * 2 + 0) * (ABUF * 2) + off,
                            afh[m2][0], afh[m2][1], afh[m2][2], afh[m2][3]);
                    ldsm_x4(sA + (u32)(st * 2 + 1) * (ABUF * 2) + off,
                            afl[m2][0], afl[m2][1], afl[m2][2], afl[m2][3]);
                }
#pragma unroll
                for (int m2 = 0; m2 < 2; m2++)
#pragma unroll
                    for (int nt = 0; nt < 4; nt++) {
                        float* a = acc[mh * 2 + m2][nt];
                        mma16816(a, afh[m2][0], afh[m2][1], afh[m2][2], afh[m2][3],
                                 bfh[nt][0], bfh[nt][1]);
                        mma16816(a, afh[m2][0], afh[m2][1], afh[m2][2], afh[m2][3],
                                 bfl[nt][0], bfl[nt][1]);
                        mma16816(a, afl[m2][0], afl[m2][1], afl[m2][2], afl[m2][3],
                                 bfh[nt][0], bfh[nt][1]);
                    }
            }
        }
        __syncthreads();
        st ^= 1;
    }

    // ---- store with N guard + optional bias ----
#pragma unroll
    for (int mt = 0; mt < 4; mt++) {
        int row0 = bm + wm + mt * 16 + (lane >> 2);
#pragma unroll
        for (int nt = 0; nt < 4; nt++) {
            int col = bn + wn + nt * 8 + (lane & 3) * 2;
            if (col < N) {
                float b0 = bias ? bias[col] : 0.f;
                float b1 = bias ? bias[col + 1] : 0.f;
                float2 v0 = make_float2(acc[mt][nt][0] + b0, acc[mt][nt][1] + b1);
                float2 v1 = make_float2(acc[mt][nt][2] + b0, acc[mt][nt][3] + b1);
                *reinterpret_cast<float2*>(&C[(size_t)row0 * N + col]) = v0;
                *reinterpret_cast<float2*>(&C[(size_t)(row0 + 8) * N + col]) = v1;
            }
        }
    }

    // ---- fused attention-logit reduction (alpha) ----
    if (attS) {
        int head = (bn + wn) >> 8;    // warp's 32-col span never crosses a 256 boundary
#pragma unroll
        for (int mt = 0; mt < 4; mt++) {
            int row0 = bm + wm + mt * 16 + (lane >> 2);
            float s0 = 0.f, d0 = 0.f, s1 = 0.f, d1 = 0.f;
#pragma unroll
            for (int nt = 0; nt < 4; nt++) {
                int col = bn + wn + nt * 8 + (lane & 3) * 2;
                float a0 = attS[col], a1 = attS[col + 1];
                float e0 = attD[col], e1 = attD[col + 1];
                s0 += acc[mt][nt][0] * a0 + acc[mt][nt][1] * a1;
                d0 += acc[mt][nt][0] * e0 + acc[mt][nt][1] * e1;
                s1 += acc[mt][nt][2] * a0 + acc[mt][nt][3] * a1;
                d1 += acc[mt][nt][2] * e0 + acc[mt][nt][3] * e1;
            }
#pragma unroll
            for (int o = 1; o < 4; o <<= 1) {
                s0 += __shfl_xor_sync(0xffffffffu, s0, o);
                d0 += __shfl_xor_sync(0xffffffffu, d0, o);
                s1 += __shfl_xor_sync(0xffffffffu, s1, o);
                d1 += __shfl_xor_sync(0xffffffffu, d1, o);
            }
            if ((lane & 3) == 0) {
                atomicAdd(&outS[(size_t)row0 * nh + head], s0);
                atomicAdd(&outD[(size_t)row0 * nh + head], d0);
                atomicAdd(&outS[(size_t)(row0 + 8) * nh + head], s1);
                atomicAdd(&outD[(size_t)(row0 + 8) * nh + head], d1);
            }
        }
    }
}

// ---------------- split conversions ----------------
__global__ void k_split(const float* __restrict__ x, __nv_bfloat16* __restrict__ hi,
                        __nv_bfloat16* __restrict__ lo, int n)
{
    int i = blockIdx.x * blockDim.x + threadIdx.x;
    if (i < n) { __nv_bfloat16 h, l; split_bf16(x[i], h, l); hi[i] = h; lo[i] = l; }
}
__global__ void k_splitT(const float* __restrict__ W, __nv_bfloat16* __restrict__ hiT,
                         __nv_bfloat16* __restrict__ loT, int K, int N)
{
    __shared__ float tile[32][33];
    int k0 = blockIdx.y * 32, n0 = blockIdx.x * 32;
    int tx = threadIdx.x, ty = threadIdx.y;
    for (int i = ty; i < 32; i += 8)
        tile[i][tx] = W[(size_t)(k0 + i) * N + n0 + tx];
    __syncthreads();
    for (int i = ty; i < 32; i += 8) {
        float v = tile[tx][i];
        __nv_bfloat16 h, l; split_bf16(v, h, l);
        size_t o = (size_t)(n0 + i) * K + k0 + tx;
        hiT[o] = h; loT[o] = l;
    }
}

// ---------------- embedding gather + split + alpha1 zeroing ----------------
__global__ void k_gather_x0(const int* __restrict__ ids, const float* __restrict__ emb,
                            __nv_bfloat16* __restrict__ x0h, __nv_bfloat16* __restrict__ x0l,
                            float* __restrict__ as1, float* __restrict__ ad1)
{
    int i = blockIdx.x, t = threadIdx.x;
    if (t < NHEADS) { as1[i * NHEADS + t] = 0.f; ad1[i * NHEADS + t] = 0.f; }
    int id = ids[i];
    float v = (id == 0) ? 0.f : emb[(size_t)id * Hd + t];
    __nv_bfloat16 h, l; split_bf16(v, h, l);
    x0h[(size_t)i * Hd + t] = h;
    x0l[(size_t)i * Hd + t] = l;
}

// ---------------- CSR build ----------------
__global__ void k_init_counts(int* __restrict__ counts)
{
    int i = blockIdx.x * blockDim.x + threadIdx.x;
    if (i < Nn) counts[i] = 1;
}
__global__ void k_count_edges(const int* __restrict__ ei, int* __restrict__ counts)
{
    int e = blockIdx.x * blockDim.x + threadIdx.x;
    if (e < Ee) atomicAdd(&counts[ei[Ee + e]], 1);
}
__global__ void k_scan16k(const int* __restrict__ counts, int* __restrict__ rowptr,
                          int* __restrict__ cursor)
{
    __shared__ int wsum[32];
    const int tid = threadIdx.x;
    const int per = Nn / 1024;
    const int base = tid * per;
    int c[16];
    int tot = 0;
#pragma unroll
    for (int u = 0; u < per; u++) { c[u] = counts[base + u]; tot += c[u]; }
    int lane = tid & 31, wid = tid >> 5;
    int v = tot;
#pragma unroll
    for (int o = 1; o < 32; o <<= 1) {
        int t2 = __shfl_up_sync(0xffffffffu, v, o);
        if (lane >= o) v += t2;
    }
    if (lane == 31) wsum[wid] = v;
    __syncthreads();
    if (wid == 0) {
        int w = wsum[lane];
#pragma unroll
        for (int o = 1; o < 32; o <<= 1) {
            int t2 = __shfl_up_sync(0xffffffffu, w, o);
            if (lane >= o) w += t2;
        }
        wsum[lane] = w;
    }
    __syncthreads();
    int run = (v - tot) + (wid > 0 ? wsum[wid - 1] : 0);
#pragma unroll
    for (int u = 0; u < per; u++) {
        rowptr[base + u] = run;
        cursor[base + u] = run;
        run += c[u];
    }
    if (tid == 1023) rowptr[Nn] = run;
}
__global__ void k_scatter_edges(const int* __restrict__ ei,
                                int* __restrict__ cursor, int* __restrict__ colsrc)
{
    int e = blockIdx.x * blockDim.x + threadIdx.x;
    if (e < Ee) {
        int d = ei[Ee + e];
        int p = atomicAdd(&cursor[d], 1);
        colsrc[p] = ei[e];
    }
}
__global__ void k_scatter_loops(int* __restrict__ cursor, int* __restrict__ colsrc)
{
    int i = blockIdx.x * blockDim.x + threadIdx.x;
    if (i < Nn) {
        int p = atomicAdd(&cursor[i], 1);
        colsrc[p] = i;
    }
}

// ---------------- GAT aggregation (two-pass softmax, fused bf16 split) ----------------
__global__ void k_gat1_agg(const float* __restrict__ h1,
                           const float* __restrict__ aS, const float* __restrict__ aD,
                           const int* __restrict__ rowptr, const int* __restrict__ colsrc,
                           const float* __restrict__ b1,
                           __nv_bfloat16* __restrict__ x1h, __nv_bfloat16* __restrict__ x1l)
{
    int dst = blockIdx.x;
    int w = threadIdx.x >> 5, lane = threadIdx.x & 31;
    int beg = rowptr[dst], end = rowptr[dst + 1];
    float adv = aD[dst * NHEADS + w];

    float m = -3.4e38f;
    for (int e = beg; e < end; e++) {
        float v = aS[colsrc[e] * NHEADS + w] + adv;
        v = v > 0.f ? v : 0.2f * v;
        m = fmaxf(m, v);
    }
    float acc[8] = {0.f, 0.f, 0.f, 0.f, 0.f, 0.f, 0.f, 0.f};
    float sump = 0.f;
    for (int e = beg; e < end; e++) {
        int s = colsrc[e];
        float v = aS[s * NHEADS + w] + adv;
        v = v > 0.f ? v : 0.2f * v;
        float p = expf(v - m);
        sump += p;
        const float* hp = h1 + (size_t)s * F1 + w * Hd + lane;
#pragma unroll
        for (int u = 0; u < 8; u++) acc[u] += p * hp[u * 32];
    }
    float inv = 1.f / (sump + 1e-16f);
    size_t base = (size_t)dst * F1 + w * Hd + lane;
    const float* bp = b1 + w * Hd + lane;
#pragma unroll
    for (int u = 0; u < 8; u++) {
        float o = acc[u] * inv + bp[u * 32];
        o = o > 0.f ? o : expm1f(o);           // ELU
        __nv_bfloat16 h, l; split_bf16(o, h, l);
        x1h[base + u * 32] = h;
        x1l[base + u * 32] = l;
    }
}

__global__ void k_gat2_agg(const float* __restrict__ h2,
                           const float* __restrict__ aS, const float* __restrict__ aD,
                           const int* __restrict__ rowptr, const int* __restrict__ colsrc,
                           const float* __restrict__ b2,
                           __nv_bfloat16* __restrict__ o2h, __nv_bfloat16* __restrict__ o2l)
{
    int dst = blockIdx.x, t = threadIdx.x;
    int beg = rowptr[dst], end = rowptr[dst + 1];
    float adv = aD[dst];
    float m = -3.4e38f;
    for (int e = beg; e < end; e++) {
        float v = aS[colsrc[e]] + adv;
        v = v > 0.f ? v : 0.2f * v;
        m = fmaxf(m, v);
    }
    float acc = 0.f, sump = 0.f;
    for (int e = beg; e < end; e++) {
        int s = colsrc[e];
        float v = aS[s] + adv;
        v = v > 0.f ? v : 0.2f * v;
        float p = expf(v - m);
        sump += p;
        acc += p * h2[(size_t)s * Hd + t];
    }
    float o = acc / (sump + 1e-16f) + b2[t];
    __nv_bfloat16 h, l; split_bf16(o, h, l);
    o2h[(size_t)dst * Hd + t] = h;
    o2l[(size_t)dst * Hd + t] = l;
}

// ---------------- sequence bookkeeping (+ alpha2 zeroing) ----------------
__global__ void k_init_misc(int* __restrict__ len, const float* __restrict__ bih,
                            const float* __restrict__ bhh, float* __restrict__ bs,
                            float* __restrict__ h, float* __restrict__ as2,
                            float* __restrict__ ad2)
{
    int i = blockIdx.x * blockDim.x + threadIdx.x;
    if (i < Bsz) len[i] = 0;
    if (i < G4) bs[i] = bih[i] + bhh[i];
    if (i < Nn) { as2[i] = 0.f; ad2[i] = 0.f; }
    h[i] = 0.f;
}
__global__ void k_count_len(const int* __restrict__ batch, int* __restrict__ len)
{
    int i = blockIdx.x * blockDim.x + threadIdx.x;
    if (i < Nn) atomicAdd(&len[batch[i]], 1);
}
__global__ void k_scan256(const int* __restrict__ len, int* __restrict__ starts)
{
    __shared__ int wsum[8];
    int tid = threadIdx.x;
    int orig = len[tid];
    int v = orig;
    int lane = tid & 31, wid = tid >> 5;
#pragma unroll
    for (int o = 1; o < 32; o <<= 1) {
        int t2 = __shfl_up_sync(0xffffffffu, v, o);
        if (lane >= o) v += t2;
    }
    if (lane == 31) wsum[wid] = v;
    __syncthreads();
    if (tid == 0) {
        int s = 0;
#pragma unroll
        for (int u = 0; u < 8; u++) { int t2 = wsum[u]; wsum[u] = s; s += t2; }
    }
    __syncthreads();
    starts[tid] = (v - orig) + wsum[wid];
}
__global__ void k_nodeidx(const int* __restrict__ batch, const int* __restrict__ starts,
                          int* __restrict__ nodeidx)
{
    int i = blockIdx.x * blockDim.x + threadIdx.x;
    if (i < Nn) {
        int b = batch[i];
        int p = i - starts[b];
        if (p >= 0 && p < Lseq) nodeidx[b * Lseq + p] = i;
    }
}

// ---------------- persistent fused LSTM (tensor-core bf16x3 step GEMM) ----------------
#define LW 264
#define HPW 260
#define GSW 33
#define LSTM_SMEM_BYTES ((2*64*LW + 2*32*LW) * 2 + (32*HPW + 64*GSW + 512) * 4)

__global__ void __launch_bounds__(256, 1)
k_lstm(const float* __restrict__ xg, const int* __restrict__ nodeidx,
       const int* __restrict__ len, float* __restrict__ hbuf0,
       float* __restrict__ hbuf1, const float* __restrict__ Whh)
{
    extern __shared__ char smB[];
    __nv_bfloat16* WshH = (__nv_bfloat16*)smB;
    __nv_bfloat16* WshL = WshH + 64 * LW;
    __nv_bfloat16* HshH = WshL + 64 * LW;
    __nv_bfloat16* HshL = HshH + 32 * LW;
    float* Hprev = (float*)(HshL + 32 * LW);
    float* gsh   = Hprev + 32 * HPW;
    float* csh   = gsh + 64 * GSW;

    const int tid  = threadIdx.x;
    const int jb   = blockIdx.x & 15;
    const int mb   = blockIdx.x >> 4;
    const int warp = tid >> 5, lane = tid & 31;
    const int mw   = warp >> 1;
    const int nw   = warp & 1;

    unsigned* grp_arr = &g_grp_arrive[mb * 32];
    unsigned* grp_gen = &g_grp_gen[mb * 32];
    unsigned my_gen = atomicAdd(grp_gen, 0u);

    for (int idx = tid; idx < 64 * 256; idx += 256) {
        int r = idx >> 8;
        int k = idx & 255;
        int g = r >> 4, u = r & 15;
        float v = Whh[(size_t)(g * 256 + jb * 16 + u) * 256 + k];
        __nv_bfloat16 h, l; split_bf16(v, h, l);
        WshH[r * LW + k] = h;
        WshL[r * LW + k] = l;
    }
    if (tid < 256) { csh[tid] = 0.f; csh[tid + 256] = 0.f; }

    const u32 sWH = smem_u32(WshH);
    const u32 sWL = smem_u32(WshL);
    const u32 sHH = smem_u32(HshH);
    const u32 sHL = smem_u32(HshL);

    for (int t = 0; t < Lseq; t++) {
        const float* hc = (t & 1) ? hbuf1 : hbuf0;
#pragma unroll
        for (int l = 0; l < 8; l++) {
            int i4 = tid + l * 256;
            int bl = i4 >> 6;
            int k4 = (i4 & 63) * 4;
            float4 v = *(const float4*)&hc[(size_t)(mb * 32 + bl) * 256 + k4];
            *(float4*)&Hprev[bl * HPW + k4] = v;
            __nv_bfloat16 h0, l0, h1b, l1b, h2b, l2b, h3b, l3b;
            split_bf16(v.x, h0, l0);  split_bf16(v.y, h1b, l1b);
            split_bf16(v.z, h2b, l2b); split_bf16(v.w, h3b, l3b);
            __nv_bfloat16* ph = &HshH[bl * LW + k4];
            __nv_bfloat16* pl = &HshL[bl * LW + k4];
            ph[0] = h0; ph[1] = h1b; ph[2] = h2b; ph[3] = h3b;
            pl[0] = l0; pl[1] = l1b; pl[2] = l2b; pl[3] = l3b;
        }
        __syncthreads();

        float acc[2][4];
#pragma unroll
        for (int nt = 0; nt < 2; nt++)
#pragma unroll
            for (int u = 0; u < 4; u++) acc[nt][u] = 0.f;

#pragma unroll
        for (int ks = 0; ks < 16; ks++) {
            const int kb = ks * 16;
            u32 aoff = (u32)(((mw * 16 + (lane & 15)) * LW + kb + (lane >> 4) * 8) * 2);
            u32 ah0, ah1, ah2, ah3, al0, al1, al2, al3;
            ldsm_x4(sWH + aoff, ah0, ah1, ah2, ah3);
            ldsm_x4(sWL + aoff, al0, al1, al2, al3);
            int g = lane >> 3;
            u32 boff = (u32)(((nw * 16 + (g & 1) * 8 + (lane & 7)) * LW + kb + (g >> 1) * 8) * 2);
            u32 r0, r1, r2, r3;
            u32 bh[2][2], blo[2][2];
            ldsm_x4(sHH + boff, r0, r1, r2, r3);
            bh[0][0] = r0; bh[1][0] = r1; bh[0][1] = r2; bh[1][1] = r3;
            ldsm_x4(sHL + boff, r0, r1, r2, r3);
            blo[0][0] = r0; blo[1][0] = r1; blo[0][1] = r2; blo[1][1] = r3;
#pragma unroll
            for (int nt = 0; nt < 2; nt++) {
                mma16816(acc[nt], ah0, ah1, ah2, ah3, bh[nt][0], bh[nt][1]);
                mma16816(acc[nt], ah0, ah1, ah2, ah3, blo[nt][0], blo[nt][1]);
                mma16816(acc[nt], al0, al1, al2, al3, bh[nt][0], bh[nt][1]);
            }
        }

        {
            int grow = mw * 16 + (lane >> 2);
#pragma unroll
            for (int nt = 0; nt < 2; nt++) {
                int col = nw * 16 + nt * 8 + (lane & 3) * 2;
                gsh[grow * GSW + col]           = acc[nt][0];
                gsh[grow * GSW + col + 1]       = acc[nt][1];
                gsh[(grow + 8) * GSW + col]     = acc[nt][2];
                gsh[(grow + 8) * GSW + col + 1] = acc[nt][3];
            }
        }
        __syncthreads();

        float* hn_buf = (t & 1) ? hbuf0 : hbuf1;
#pragma unroll
        for (int p = tid; p < 512; p += 256) {
            int u = p & 15;
            int bl = p >> 4;
            int bglob = mb * 32 + bl;
            int node = nodeidx[bglob * Lseq + t];
            const float* xp = xg + (size_t)node * G4 + jb * 16 + u;
            float gi = gsh[(0  + u) * GSW + bl] + xp[0];
            float gf = gsh[(16 + u) * GSW + bl] + xp[256];
            float gg = gsh[(32 + u) * GSW + bl] + xp[512];
            float go = gsh[(48 + u) * GSW + bl] + xp[768];
            float hprev = Hprev[bl * HPW + jb * 16 + u];
            float cprev = csh[u * 32 + bl];
            float si = 1.f / (1.f + expf(-gi));
            float sf = 1.f / (1.f + expf(-gf));
            float so = 1.f / (1.f + expf(-go));
            float cn = sf * cprev + si * tanhf(gg);
            float hn = so * tanhf(cn);
            bool act = (t < len[bglob]);
            if (act) csh[u * 32 + bl] = cn;
            float hw = act ? hn : hprev;
            __stcg(&hn_buf[bglob * 256 + jb * 16 + u], hw);
            if (t == Lseq - 1) {
                __nv_bfloat16 sh, sl; split_bf16(hw, sh, sl);
                g_hTh[bglob * 256 + jb * 16 + u] = sh;
                g_hTl[bglob * 256 + jb * 16 + u] = sl;
            }
        }

        if (t != Lseq - 1) {
            __threadfence();
            __syncthreads();
            if (tid == 0) {
                unsigned old = atomicAdd(grp_arr, 1u);
                if (old == 15u) {
                    atomicExch(grp_arr, 0u);
                    __threadfence();
                    atomicAdd(grp_gen, 1u);
                } else {
                    while (atomicAdd(grp_gen, 0u) == my_gen) { }
                }
            }
            __syncthreads();
            my_gen++;
        }
    }
}

// ---------------- host launcher ----------------
extern "C" void kernel_launch(void* const* d_in, const int* in_sizes, int n_in,
                              void* d_out, int out_size)
{
    const int*   x_ids = (const int*)d_in[0];
    const int*   ei    = (const int*)d_in[1];
    const int*   batch = (const int*)d_in[2];
    const float* emb   = (const float*)d_in[3];
    const float* W1    = (const float*)d_in[4];
    const float* attS1 = (const float*)d_in[5];
    const float* attD1 = (const float*)d_in[6];
    const float* b1    = (const float*)d_in[7];
    const float* W2    = (const float*)d_in[8];
    const float* attS2 = (const float*)d_in[9];
    const float* attD2 = (const float*)d_in[10];
    const float* b2    = (const float*)d_in[11];
    const float* Wih   = (const float*)d_in[12];
    const float* Whh   = (const float*)d_in[13];
    const float* bih   = (const float*)d_in[14];
    const float* bhh   = (const float*)d_in[15];
    const float* Wp    = (const float*)d_in[16];
    const float* bp    = (const float*)d_in[17];
    float* out = (float*)d_out;

    void* p;
    cudaGetSymbolAddress(&p, g_h1);      float* h1   = (float*)p;
    cudaGetSymbolAddress(&p, g_h2);      float* h2   = (float*)p;
    cudaGetSymbolAddress(&p, g_xg);      float* xg   = (float*)p;
    cudaGetSymbolAddress(&p, g_as1);     float* as1  = (float*)p;
    cudaGetSymbolAddress(&p, g_ad1);     float* ad1  = (float*)p;
    cudaGetSymbolAddress(&p, g_as2);     float* as2  = (float*)p;
    cudaGetSymbolAddress(&p, g_ad2);     float* ad2  = (float*)p;
    cudaGetSymbolAddress(&p, g_counts);  int* counts = (int*)p;
    cudaGetSymbolAddress(&p, g_rowptr);  int* rowptr = (int*)p;
    cudaGetSymbolAddress(&p, g_cursor);  int* cursor = (int*)p;
    cudaGetSymbolAddress(&p, g_colsrc);  int* colsrc = (int*)p;
    cudaGetSymbolAddress(&p, g_len);     int* len    = (int*)p;
    cudaGetSymbolAddress(&p, g_starts);  int* starts = (int*)p;
    cudaGetSymbolAddress(&p, g_nodeidx); int* nodeidx= (int*)p;
    cudaGetSymbolAddress(&p, g_hbuf1);   float* hb1  = (float*)p;
    cudaGetSymbolAddress(&p, g_h);       float* hS   = (float*)p;
    cudaGetSymbolAddress(&p, g_bsum);    float* bsum = (float*)p;

    __nv_bfloat16 *x0h, *x0l, *x1h, *x1l, *o2h, *o2l;
    __nv_bfloat16 *W1Th, *W1Tl, *W2Th, *W2Tl, *Wihh, *Wihl, *hTh, *hTl, *Wph, *Wpl;
    cudaGetSymbolAddress(&p, g_x0h); x0h = (__nv_bfloat16*)p;
    cudaGetSymbolAddress(&p, g_x0l); x0l = (__nv_bfloat16*)p;
    cudaGetSymbolAddress(&p, g_x1h); x1h = (__nv_bfloat16*)p;
    cudaGetSymbolAddress(&p, g_x1l); x1l = (__nv_bfloat16*)p;
    cudaGetSymbolAddress(&p, g_o2h); o2h = (__nv_bfloat16*)p;
    cudaGetSymbolAddress(&p, g_o2l); o2l = (__nv_bfloat16*)p;
    cudaGetSymbolAddress(&p, g_W1Th); W1Th = (__nv_bfloat16*)p;
    cudaGetSymbolAddress(&p, g_W1Tl); W1Tl = (__nv_bfloat16*)p;
    cudaGetSymbolAddress(&p, g_W2Th); W2Th = (__nv_bfloat16*)p;
    cudaGetSymbolAddress(&p, g_W2Tl); W2Tl = (__nv_bfloat16*)p;
    cudaGetSymbolAddress(&p, g_Wihh); Wihh = (__nv_bfloat16*)p;
    cudaGetSymbolAddress(&p, g_Wihl); Wihl = (__nv_bfloat16*)p;
    cudaGetSymbolAddress(&p, g_hTh);  hTh  = (__nv_bfloat16*)p;
    cudaGetSymbolAddress(&p, g_hTl);  hTl  = (__nv_bfloat16*)p;
    cudaGetSymbolAddress(&p, g_Wph);  Wph  = (__nv_bfloat16*)p;
    cudaGetSymbolAddress(&p, g_Wpl);  Wpl  = (__nv_bfloat16*)p;

    cudaFuncSetAttribute(k_lstm, cudaFuncAttributeMaxDynamicSharedMemorySize, LSTM_SMEM_BYTES);
    cudaFuncSetAttribute(k_gemm_bf3, cudaFuncAttributeMaxDynamicSharedMemorySize, GEMM_SMEM);

    cudaStream_t s2;
    cudaStreamCreateWithFlags(&s2, cudaStreamNonBlocking);
    cudaEvent_t evFork, evJoin;
    cudaEventCreateWithFlags(&evFork, cudaEventDisableTiming);
    cudaEventCreateWithFlags(&evJoin, cudaEventDisableTiming);

    // ---- main stream: GEMM1 dependency chain ----
    k_gather_x0<<<Nn, Hd>>>(x_ids, emb, x0h, x0l, as1, ad1);
    k_splitT<<<dim3(F1 / 32, Hd / 32), dim3(32, 8)>>>(W1, W1Th, W1Tl, Hd, F1);

    // ---- fork: all GEMM1-independent prep on s2 ----
    cudaEventRecord(evFork, 0);
    cudaStreamWaitEvent(s2, evFork, 0);
    k_splitT<<<dim3(Hd / 32, F1 / 32), dim3(32, 8), 0, s2>>>(W2, W2Th, W2Tl, F1, Hd);
    k_split<<<(G4 * Hd + 255) / 256, 256, 0, s2>>>(Wih, Wihh, Wihl, G4 * Hd);
    k_split<<<(NNODE_ * Hd + 255) / 256, 256, 0, s2>>>(Wp, Wph, Wpl, NNODE_ * Hd);
    k_init_counts<<<Nn / 256, 256, 0, s2>>>(counts);
    k_count_edges<<<Ee / 256, 256, 0, s2>>>(ei, counts);
    k_scan16k<<<1, 1024, 0, s2>>>(counts, rowptr, cursor);
    k_scatter_edges<<<Ee / 256, 256, 0, s2>>>(ei, cursor, colsrc);
    k_scatter_loops<<<Nn / 256, 256, 0, s2>>>(cursor, colsrc);
    k_init_misc<<<(Bsz * Hd) / 256, 256, 0, s2>>>(len, bih, bhh, bsum, hS, as2, ad2);
    k_count_len<<<Nn / 256, 256, 0, s2>>>(batch, len);
    k_scan256<<<1, Bsz, 0, s2>>>(len, starts);
    k_nodeidx<<<Nn / 256, 256, 0, s2>>>(batch, starts, nodeidx);
    cudaEventRecord(evJoin, s2);

    // ---- main stream continues in parallel: GEMM1 with fused alpha1 ----
    k_gemm_bf3<<<dim3(F1 / GBN, Nn / GBM), 256, GEMM_SMEM>>>(
        x0h, x0l, W1Th, W1Tl, h1, Nn, F1, Hd, nullptr,
        attS1, attD1, as1, ad1, NHEADS);

    // ---- join: gat1 needs the CSR (and alpha zero-init happened pre-GEMM1) ----
    cudaStreamWaitEvent(0, evJoin, 0);

    k_gat1_agg<<<Nn, 256>>>(h1, as1, ad1, rowptr, colsrc, b1, x1h, x1l);

    // GEMM2 with fused alpha2 (as2/ad2 zeroed in k_init_misc on s2, before join)
    k_gemm_bf3<<<dim3(Hd / GBN, Nn / GBM), 256, GEMM_SMEM>>>(
        x1h, x1l, W2Th, W2Tl, h2, Nn, Hd, F1, nullptr,
        attS2, attD2, as2, ad2, 1);

    k_gat2_agg<<<Nn, 256>>>(h2, as2, ad2, rowptr, colsrc, b2, o2h, o2l);

    k_gemm_bf3<<<dim3(G4 / GBN, Nn / GBM), 256, GEMM_SMEM>>>(
        o2h, o2l, Wihh, Wihl, xg, Nn, G4, Hd, bsum,
        nullptr, nullptr, nullptr, nullptr, 0);

    k_lstm<<<LSTM_BLOCKS, 256, LSTM_SMEM_BYTES>>>(xg, nodeidx, len, hS, hb1, Whh);

    // final GEMM reads hTh/hTl written directly by the LSTM's last step
    k_gemm_bf3<<<dim3((NNODE_ + GBN - 1) / GBN, Bsz / GBM), 256, GEMM_SMEM>>>(
        hTh, hTl, Wph, Wpl, out, Bsz, NNODE_, Hd, bp,
        nullptr, nullptr, nullptr, nullptr, 0);
}